// round 1
// baseline (speedup 1.0000x reference)
#include <cuda_runtime.h>
#include <math.h>

// ---------------- problem constants ----------------
#define Bc    32
#define Sc    512
#define Hc    768
#define Wc    128
#define Gc    4
#define NHc   4
#define HDc   192
#define FFc   2048
#define NLc   2
#define NLABc 6
#define Lwc   (Wc + 1)          // 129
#define Mc    (Bc * Lwc)        // 4128
#define EPSc  1e-5f
#define SCALEc 0.07216878364870322f  // 1/sqrt(192)

// ---------------- scratch (device globals; no allocs) ----------------
__device__ float g_x  [Mc * Hc];        // activations [M, H]
__device__ float g_qkv[Mc * 3 * Hc];    // [M, 3H]
__device__ float g_ctx[Mc * Hc];        // attention context
__device__ float g_y  [Mc * Hc];        // gemm out (proj / ff2)
__device__ float g_ff [Mc * FFc];       // ff1 output

// ---------------- build x = [cls ; word embeddings] ----------------
__global__ __launch_bounds__(256) void build_x_kernel(
    const float* __restrict__ hidden, const int* __restrict__ wti,
    const int* __restrict__ gmask, const int* __restrict__ wvalid,
    float* __restrict__ x)
{
    int w = blockIdx.x, b = blockIdx.y, t = threadIdx.x;
    float* xr = x + (size_t)(b * Lwc + w) * Hc;
    if (w == 0) {
        const float* hr = hidden + (size_t)(b * Sc) * Hc;
        for (int j = t; j < Hc; j += 256) xr[j] = hr[j];
        return;
    }
    int wi = w - 1;
    int valid = wvalid[b * Wc + wi];
    const float* hrows[Gc];
    float m[Gc];
    float cnt = 0.f;
#pragma unroll
    for (int g = 0; g < Gc; g++) {
        int idx = wti[(b * Wc + wi) * Gc + g];
        hrows[g] = hidden + (size_t)(b * Sc + idx) * Hc;
        m[g] = gmask[(b * Wc + wi) * Gc + g] ? 1.f : 0.f;
        cnt += m[g];
    }
    float inv = valid ? (1.f / fmaxf(cnt, 1.f)) : 0.f;
    for (int j = t; j < Hc; j += 256) {
        float s = 0.f;
#pragma unroll
        for (int g = 0; g < Gc; g++) s += m[g] * hrows[g][j];
        xr[j] = s * inv;
    }
}

// ---------------- SGEMM: C[M,N] = A[M,K] @ Wt[N,K]^T + bias (+ReLU) ----------------
// tile 128x64, BK=16, 256 threads, 8x4 microtile. N%64==0, K%16==0 guaranteed.
#define BMg 128
#define BNg 64
#define BKg 16

template <bool RELU>
__global__ __launch_bounds__(256) void gemm_bias_kernel(
    const float* __restrict__ A, const float* __restrict__ Wt,
    const float* __restrict__ bias, float* __restrict__ C,
    int M, int N, int K)
{
    __shared__ float As[BKg][BMg];
    __shared__ float Bs[BKg][BNg];
    int tid = threadIdx.x;
    int tx = tid & 15;   // col group: 16 * 4 = 64
    int ty = tid >> 4;   // row group: 16 * 8 = 128
    int row0 = blockIdx.y * BMg;
    int col0 = blockIdx.x * BNg;

    float acc[8][4];
#pragma unroll
    for (int i = 0; i < 8; i++)
#pragma unroll
        for (int j = 0; j < 4; j++) acc[i][j] = 0.f;

    for (int k0 = 0; k0 < K; k0 += BKg) {
        // A tile: 128x16 = 512 float4, 2 per thread
#pragma unroll
        for (int i = 0; i < 2; i++) {
            int idx4 = tid + i * 256;
            int c4 = idx4 & 3;
            int r  = idx4 >> 2;
            int grow = row0 + r;
            float4 v = make_float4(0.f, 0.f, 0.f, 0.f);
            if (grow < M) v = *(const float4*)(A + (size_t)grow * K + k0 + c4 * 4);
            As[c4 * 4 + 0][r] = v.x; As[c4 * 4 + 1][r] = v.y;
            As[c4 * 4 + 2][r] = v.z; As[c4 * 4 + 3][r] = v.w;
        }
        // B tile: 64x16 = 256 float4, 1 per thread
        {
            int c4 = tid & 3;
            int n  = tid >> 2;
            float4 v = *(const float4*)(Wt + (size_t)(col0 + n) * K + k0 + c4 * 4);
            Bs[c4 * 4 + 0][n] = v.x; Bs[c4 * 4 + 1][n] = v.y;
            Bs[c4 * 4 + 2][n] = v.z; Bs[c4 * 4 + 3][n] = v.w;
        }
        __syncthreads();
#pragma unroll
        for (int kk = 0; kk < BKg; kk++) {
            float ra[8], rb[4];
#pragma unroll
            for (int i = 0; i < 8; i++) ra[i] = As[kk][ty * 8 + i];
#pragma unroll
            for (int j = 0; j < 4; j++) rb[j] = Bs[kk][tx * 4 + j];
#pragma unroll
            for (int i = 0; i < 8; i++)
#pragma unroll
                for (int j = 0; j < 4; j++) acc[i][j] += ra[i] * rb[j];
        }
        __syncthreads();
    }
#pragma unroll
    for (int i = 0; i < 8; i++) {
        int grow = row0 + ty * 8 + i;
        if (grow < M) {
#pragma unroll
            for (int j = 0; j < 4; j++) {
                int gcol = col0 + tx * 4 + j;
                float v = acc[i][j] + bias[gcol];
                if (RELU) v = fmaxf(v, 0.f);
                C[(size_t)grow * N + gcol] = v;
            }
        }
    }
}

// ---------------- attention: one block per (q, h, b) ----------------
__global__ __launch_bounds__(192) void attn_kernel(
    const float* __restrict__ qkv, const int* __restrict__ wvalid,
    float* __restrict__ ctx)
{
    int qi = blockIdx.x, h = blockIdx.y, b = blockIdx.z;
    int t = threadIdx.x;
    __shared__ float sq[HDc];
    __shared__ float sa[Lwc];
    __shared__ float sinv;
    const int row3H = 3 * Hc;

    sq[t] = qkv[(size_t)(b * Lwc + qi) * row3H + h * HDc + t];
    __syncthreads();

    if (t < Lwc) {
        bool valid = (t == 0) || (wvalid[b * Wc + (t - 1)] != 0);
        float s = -1e30f;
        if (valid) {
            const float* kp = qkv + (size_t)(b * Lwc + t) * row3H + Hc + h * HDc;
            float acc = 0.f;
#pragma unroll 4
            for (int d = 0; d < HDc; d++) acc += sq[d] * kp[d];
            s = acc * SCALEc;
        }
        sa[t] = s;
    }
    __syncthreads();

    if (t < 32) {
        float m = -1e30f;
        for (int k = t; k < Lwc; k += 32) m = fmaxf(m, sa[k]);
#pragma unroll
        for (int o = 16; o > 0; o >>= 1) m = fmaxf(m, __shfl_xor_sync(0xffffffff, m, o));
        float sum = 0.f;
        for (int k = t; k < Lwc; k += 32) { float e = __expf(sa[k] - m); sa[k] = e; sum += e; }
#pragma unroll
        for (int o = 16; o > 0; o >>= 1) sum += __shfl_xor_sync(0xffffffff, sum, o);
        if (t == 0) sinv = 1.0f / sum;
    }
    __syncthreads();

    float inv = sinv;
    float acc = 0.f;
    const float* vp = qkv + (size_t)(b * Lwc) * row3H + 2 * Hc + h * HDc + t;
    for (int k = 0; k < Lwc; k++) acc += sa[k] * vp[(size_t)k * row3H];
    ctx[(size_t)(b * Lwc + qi) * Hc + h * HDc + t] = acc * inv;
}

// ---------------- residual add + layernorm (in-place into out) ----------------
__global__ __launch_bounds__(256) void add_ln_kernel(
    const float* __restrict__ base, const float* __restrict__ delta,
    const float* __restrict__ sc, const float* __restrict__ bi,
    float* __restrict__ out)
{
    int row = blockIdx.x, t = threadIdx.x;
    const float* xb = base + (size_t)row * Hc;
    const float* db = delta + (size_t)row * Hc;
    float v[3];
    float s = 0.f, ss = 0.f;
#pragma unroll
    for (int i = 0; i < 3; i++) {
        float a = xb[t + i * 256] + db[t + i * 256];
        v[i] = a; s += a; ss += a * a;
    }
    __shared__ float rs[32], rss[32];
#pragma unroll
    for (int o = 16; o > 0; o >>= 1) {
        s  += __shfl_down_sync(0xffffffff, s, o);
        ss += __shfl_down_sync(0xffffffff, ss, o);
    }
    int wid = t >> 5, lane = t & 31;
    if (lane == 0) { rs[wid] = s; rss[wid] = ss; }
    __syncthreads();
    if (wid == 0) {
        s  = (lane < 8) ? rs[lane]  : 0.f;
        ss = (lane < 8) ? rss[lane] : 0.f;
#pragma unroll
        for (int o = 4; o > 0; o >>= 1) {
            s  += __shfl_down_sync(0xffffffff, s, o);
            ss += __shfl_down_sync(0xffffffff, ss, o);
        }
        if (lane == 0) { rs[0] = s; rss[0] = ss; }
    }
    __syncthreads();
    float mean = rs[0] * (1.f / Hc);
    float var  = rss[0] * (1.f / Hc) - mean * mean;
    float r = rsqrtf(var + EPSc);
#pragma unroll
    for (int i = 0; i < 3; i++) {
        int j = t + i * 256;
        out[(size_t)row * Hc + j] = (v[i] - mean) * r * sc[j] + bi[j];
    }
}

// ---------------- classifier + pooled output ----------------
// out layout: [logits(B*NLAB) | pooled(B*H)]
__global__ __launch_bounds__(256) void cls_kernel(
    const float* __restrict__ x, const float* __restrict__ cw,
    const float* __restrict__ cb, float* __restrict__ out)
{
    int b = blockIdx.x, t = threadIdx.x;
    const float* p = x + (size_t)(b * Lwc) * Hc;
    for (int j = t; j < Hc; j += 256) out[Bc * NLABc + b * Hc + j] = p[j];
    int wid = t >> 5, lane = t & 31;
    if (wid < NLABc) {
        float s = 0.f;
        for (int j = lane; j < Hc; j += 32) s += p[j] * cw[wid * Hc + j];
#pragma unroll
        for (int o = 16; o > 0; o >>= 1) s += __shfl_down_sync(0xffffffff, s, o);
        if (lane == 0) out[b * NLABc + wid] = s + cb[wid];
    }
}

// ---------------- host ----------------
static float* symaddr(const void* sym) {
    void* p = nullptr;
    cudaGetSymbolAddress(&p, sym);
    return (float*)p;
}

extern "C" void kernel_launch(void* const* d_in, const int* in_sizes, int n_in,
                              void* d_out, int out_size)
{
    const float* hidden = (const float*)d_in[0];
    const int*   wti    = (const int*)  d_in[1];
    const int*   gmask  = (const int*)  d_in[2];
    const int*   wvalid = (const int*)  d_in[3];
    const float* qkv_w  = (const float*)d_in[4];
    const float* qkv_b  = (const float*)d_in[5];
    const float* out_w  = (const float*)d_in[6];
    const float* out_b  = (const float*)d_in[7];
    const float* ff1_w  = (const float*)d_in[8];
    const float* ff1_b  = (const float*)d_in[9];
    const float* ff2_w  = (const float*)d_in[10];
    const float* ff2_b  = (const float*)d_in[11];
    const float* ln1_s  = (const float*)d_in[12];
    const float* ln1_b  = (const float*)d_in[13];
    const float* ln2_s  = (const float*)d_in[14];
    const float* ln2_b  = (const float*)d_in[15];
    const float* cls_w  = (const float*)d_in[16];
    const float* cls_b  = (const float*)d_in[17];
    float* out = (float*)d_out;

    float* x   = symaddr(g_x);
    float* qkv = symaddr(g_qkv);
    float* ctx = symaddr(g_ctx);
    float* y   = symaddr(g_y);
    float* ff  = symaddr(g_ff);

    // 1. build x
    build_x_kernel<<<dim3(Lwc, Bc), 256>>>(hidden, wti, gmask, wvalid, x);

    dim3 gQKV(3 * Hc / BNg, (Mc + BMg - 1) / BMg);   // (36, 33)
    dim3 gH  (Hc / BNg,     (Mc + BMg - 1) / BMg);   // (12, 33)
    dim3 gFF (FFc / BNg,    (Mc + BMg - 1) / BMg);   // (32, 33)

    for (int l = 0; l < NLc; l++) {
        gemm_bias_kernel<false><<<gQKV, 256>>>(x, qkv_w + (size_t)l * 3 * Hc * Hc,
                                               qkv_b + (size_t)l * 3 * Hc, qkv,
                                               Mc, 3 * Hc, Hc);
        attn_kernel<<<dim3(Lwc, NHc, Bc), 192>>>(qkv, wvalid, ctx);
        gemm_bias_kernel<false><<<gH, 256>>>(ctx, out_w + (size_t)l * Hc * Hc,
                                             out_b + (size_t)l * Hc, y,
                                             Mc, Hc, Hc);
        add_ln_kernel<<<Mc, 256>>>(x, y, ln1_s + (size_t)l * Hc, ln1_b + (size_t)l * Hc, x);
        gemm_bias_kernel<true><<<gFF, 256>>>(x, ff1_w + (size_t)l * FFc * Hc,
                                             ff1_b + (size_t)l * FFc, ff,
                                             Mc, FFc, Hc);
        gemm_bias_kernel<false><<<gH, 256>>>(ff, ff2_w + (size_t)l * Hc * FFc,
                                             ff2_b + (size_t)l * Hc, y,
                                             Mc, Hc, FFc);
        add_ln_kernel<<<Mc, 256>>>(x, y, ln2_s + (size_t)l * Hc, ln2_b + (size_t)l * Hc, x);
    }

    cls_kernel<<<Bc, 256>>>(x, cls_w, cls_b, out);
}

// round 3
// speedup vs baseline: 2.0355x; 2.0355x over previous
#include <cuda_runtime.h>
#include <math.h>

// ---------------- problem constants ----------------
#define Bc    32
#define Sc    512
#define Hc    768
#define Wc    128
#define Gc    4
#define NHc   4
#define HDc   192
#define FFc   2048
#define NLc   2
#define NLABc 6
#define Lwc   (Wc + 1)          // 129
#define Mc    (Bc * Lwc)        // 4128
#define EPSc  1e-5f
#define SCALEc 0.07216878364870322f  // 1/sqrt(192)

// ---------------- scratch (device globals; no allocs) ----------------
__device__ float g_x  [Mc * Hc];        // activations [M, H]
__device__ float g_qkv[Mc * 3 * Hc];    // [M, 3H]
__device__ float g_ctx[Mc * Hc];        // attention context
__device__ float g_y  [Mc * Hc];        // gemm out (proj / ff2)
__device__ float g_ff [Mc * FFc];       // ff1 output

// ---------------- build x = [cls ; word embeddings] ----------------
__global__ __launch_bounds__(256) void build_x_kernel(
    const float* __restrict__ hidden, const int* __restrict__ wti,
    const int* __restrict__ gmask, const int* __restrict__ wvalid,
    float* __restrict__ x)
{
    int w = blockIdx.x, b = blockIdx.y, t = threadIdx.x;
    float* xr = x + (size_t)(b * Lwc + w) * Hc;
    if (w == 0) {
        const float* hr = hidden + (size_t)(b * Sc) * Hc;
        for (int j = t; j < Hc; j += 256) xr[j] = hr[j];
        return;
    }
    int wi = w - 1;
    int valid = wvalid[b * Wc + wi];
    const float* hrows[Gc];
    float m[Gc];
    float cnt = 0.f;
#pragma unroll
    for (int g = 0; g < Gc; g++) {
        int idx = wti[(b * Wc + wi) * Gc + g];
        hrows[g] = hidden + (size_t)(b * Sc + idx) * Hc;
        m[g] = gmask[(b * Wc + wi) * Gc + g] ? 1.f : 0.f;
        cnt += m[g];
    }
    float inv = valid ? (1.f / fmaxf(cnt, 1.f)) : 0.f;
    for (int j = t; j < Hc; j += 256) {
        float s = 0.f;
#pragma unroll
        for (int g = 0; g < Gc; g++) s += m[g] * hrows[g][j];
        xr[j] = s * inv;
    }
}

// =====================================================================
// TF32 tensor-core GEMM: C[M,N] = A[M,K] @ Wt[N,K]^T + bias (+ReLU)
// tile 128x128x16, 256 threads, 8 warps (2x4), warp tile 64x32.
// Smem k-major with XOR swizzle: addr(k,x) = k*128 + (x ^ (8*(k&3)))
//  -> conflict-free STS (writer lanes span 32 consecutive x per k-group)
//  -> conflict-free fragment LDS for mma.m16n8k8 layouts.
// =====================================================================
#define BMt 128
#define BNt 128
#define BKt 16

__device__ __forceinline__ unsigned f2tf(float f) {
    unsigned r;
    asm("cvt.rna.tf32.f32 %0, %1;" : "=r"(r) : "f"(f));
    return r;
}

__device__ __forceinline__ void mma8(float* d, const unsigned* a, const unsigned* b) {
    asm volatile(
        "mma.sync.aligned.m16n8k8.row.col.f32.tf32.tf32.f32 "
        "{%0,%1,%2,%3}, {%4,%5,%6,%7}, {%8,%9}, {%0,%1,%2,%3};\n"
        : "+f"(d[0]), "+f"(d[1]), "+f"(d[2]), "+f"(d[3])
        : "r"(a[0]), "r"(a[1]), "r"(a[2]), "r"(a[3]),
          "r"(b[0]), "r"(b[1]));
}

template <bool RELU>
__global__ __launch_bounds__(256, 2) void gemm_tf32_kernel(
    const float* __restrict__ A, const float* __restrict__ Wt,
    const float* __restrict__ bias, float* __restrict__ C,
    int M, int N, int K)
{
    __shared__ unsigned As[2][BKt * BMt];
    __shared__ unsigned Bs[2][BKt * BMt];

    const int tid  = threadIdx.x;
    const int warp = tid >> 5;
    const int lane = tid & 31;
    const int wm = warp >> 2;       // 0..1
    const int wn = warp & 3;        // 0..3
    const int rowBase = blockIdx.y * BMt;
    const int colBase = blockIdx.x * BNt;
    const int c4 = tid >> 6;        // k-group 0..3 (constant per warp pair)
    const int ml = tid & 63;        // 0..63 (32 consecutive per warp)
    const int fr = lane >> 2;       // fragment row 0..7
    const int fc = lane & 3;        // fragment k 0..3

    float acc[4][4][4];
#pragma unroll
    for (int i = 0; i < 4; i++)
#pragma unroll
        for (int j = 0; j < 4; j++)
#pragma unroll
            for (int q = 0; q < 4; q++) acc[i][j][q] = 0.f;

    float4 pa[2], pb[2];
    const int nk = K / BKt;

    // ---- prologue: load + store tile 0 ----
    {
        const int k0 = 0;
#pragma unroll
        for (int i = 0; i < 2; i++) {
            int m = ml + 64 * i;
            int grow = rowBase + m;
            pa[i] = (grow < M) ? *(const float4*)(A + (size_t)grow * K + k0 + 4 * c4)
                               : make_float4(0.f, 0.f, 0.f, 0.f);
            pb[i] = *(const float4*)(Wt + (size_t)(colBase + m) * K + k0 + 4 * c4);
        }
#pragma unroll
        for (int i = 0; i < 2; i++) {
            int m = ml + 64 * i;
            const float* va = (const float*)&pa[i];
            const float* vb = (const float*)&pb[i];
#pragma unroll
            for (int j = 0; j < 4; j++) {
                int k = 4 * c4 + j;
                As[0][k * BMt + (m ^ (8 * j))] = f2tf(va[j]);
                Bs[0][k * BMt + (m ^ (8 * j))] = f2tf(vb[j]);
            }
        }
    }
    __syncthreads();

    int buf = 0;
    for (int t = 0; ; t++) {
        const bool has_next = (t + 1 < nk);
        if (has_next) {
            const int k0 = (t + 1) * BKt;
#pragma unroll
            for (int i = 0; i < 2; i++) {
                int m = ml + 64 * i;
                int grow = rowBase + m;
                pa[i] = (grow < M) ? *(const float4*)(A + (size_t)grow * K + k0 + 4 * c4)
                                   : make_float4(0.f, 0.f, 0.f, 0.f);
                pb[i] = *(const float4*)(Wt + (size_t)(colBase + m) * K + k0 + 4 * c4);
            }
        }
        // ---- compute on buf ----
#pragma unroll
        for (int ks = 0; ks < 2; ks++) {
            const int kk = ks * 8;
            unsigned af[4][4], bf[4][2];
            const unsigned* Ab = As[buf];
            const unsigned* Bb = Bs[buf];
            const int xr = 8 * fc;   // xor term for k = kk+fc and kk+fc+4
#pragma unroll
            for (int mt = 0; mt < 4; mt++) {
                int m0 = wm * 64 + mt * 16 + fr;
                af[mt][0] = Ab[(kk + fc) * BMt + (m0 ^ xr)];
                af[mt][1] = Ab[(kk + fc) * BMt + ((m0 + 8) ^ xr)];
                af[mt][2] = Ab[(kk + fc + 4) * BMt + (m0 ^ xr)];
                af[mt][3] = Ab[(kk + fc + 4) * BMt + ((m0 + 8) ^ xr)];
            }
#pragma unroll
            for (int nt = 0; nt < 4; nt++) {
                int n0 = wn * 32 + nt * 8 + fr;
                bf[nt][0] = Bb[(kk + fc) * BMt + (n0 ^ xr)];
                bf[nt][1] = Bb[(kk + fc + 4) * BMt + (n0 ^ xr)];
            }
#pragma unroll
            for (int mt = 0; mt < 4; mt++)
#pragma unroll
                for (int nt = 0; nt < 4; nt++)
                    mma8(acc[mt][nt], af[mt], bf[nt]);
        }
        if (!has_next) break;
        __syncthreads();
        {
            const int nb = buf ^ 1;
#pragma unroll
            for (int i = 0; i < 2; i++) {
                int m = ml + 64 * i;
                const float* va = (const float*)&pa[i];
                const float* vb = (const float*)&pb[i];
#pragma unroll
                for (int j = 0; j < 4; j++) {
                    int k = 4 * c4 + j;
                    As[nb][k * BMt + (m ^ (8 * j))] = f2tf(va[j]);
                    Bs[nb][k * BMt + (m ^ (8 * j))] = f2tf(vb[j]);
                }
            }
        }
        __syncthreads();
        buf ^= 1;
    }

    // ---- epilogue ----
#pragma unroll
    for (int mt = 0; mt < 4; mt++) {
        int row0 = rowBase + wm * 64 + mt * 16 + fr;
#pragma unroll
        for (int nt = 0; nt < 4; nt++) {
            int col = colBase + wn * 32 + nt * 8 + 2 * fc;
            float b0 = bias[col], b1 = bias[col + 1];
            if (row0 < M) {
                float v0 = acc[mt][nt][0] + b0;
                float v1 = acc[mt][nt][1] + b1;
                if (RELU) { v0 = fmaxf(v0, 0.f); v1 = fmaxf(v1, 0.f); }
                float2 o = make_float2(v0, v1);
                *(float2*)(C + (size_t)row0 * N + col) = o;
            }
            if (row0 + 8 < M) {
                float v2 = acc[mt][nt][2] + b0;
                float v3 = acc[mt][nt][3] + b1;
                if (RELU) { v2 = fmaxf(v2, 0.f); v3 = fmaxf(v3, 0.f); }
                float2 o = make_float2(v2, v3);
                *(float2*)(C + (size_t)(row0 + 8) * N + col) = o;
            }
        }
    }
}

// ---------------- attention: one block per (q, h, b) ----------------
__global__ __launch_bounds__(192) void attn_kernel(
    const float* __restrict__ qkv, const int* __restrict__ wvalid,
    float* __restrict__ ctx)
{
    int qi = blockIdx.x, h = blockIdx.y, b = blockIdx.z;
    int t = threadIdx.x;
    __shared__ float sq[HDc];
    __shared__ float sa[Lwc];
    __shared__ float sinv;
    const int row3H = 3 * Hc;

    sq[t] = qkv[(size_t)(b * Lwc + qi) * row3H + h * HDc + t];
    __syncthreads();

    if (t < Lwc) {
        bool valid = (t == 0) || (wvalid[b * Wc + (t - 1)] != 0);
        float s = -1e30f;
        if (valid) {
            const float* kp = qkv + (size_t)(b * Lwc + t) * row3H + Hc + h * HDc;
            float acc = 0.f;
#pragma unroll 4
            for (int d = 0; d < HDc; d++) acc += sq[d] * kp[d];
            s = acc * SCALEc;
        }
        sa[t] = s;
    }
    __syncthreads();

    if (t < 32) {
        float m = -1e30f;
        for (int k = t; k < Lwc; k += 32) m = fmaxf(m, sa[k]);
#pragma unroll
        for (int o = 16; o > 0; o >>= 1) m = fmaxf(m, __shfl_xor_sync(0xffffffff, m, o));
        float sum = 0.f;
        for (int k = t; k < Lwc; k += 32) { float e = __expf(sa[k] - m); sa[k] = e; sum += e; }
#pragma unroll
        for (int o = 16; o > 0; o >>= 1) sum += __shfl_xor_sync(0xffffffff, sum, o);
        if (t == 0) sinv = 1.0f / sum;
    }
    __syncthreads();

    float inv = sinv;
    float acc = 0.f;
    const float* vp = qkv + (size_t)(b * Lwc) * row3H + 2 * Hc + h * HDc + t;
    for (int k = 0; k < Lwc; k++) acc += sa[k] * vp[(size_t)k * row3H];
    ctx[(size_t)(b * Lwc + qi) * Hc + h * HDc + t] = acc * inv;
}

// ---------------- residual add + layernorm ----------------
__global__ __launch_bounds__(256) void add_ln_kernel(
    const float* __restrict__ base, const float* __restrict__ delta,
    const float* __restrict__ sc, const float* __restrict__ bi,
    float* __restrict__ out)
{
    int row = blockIdx.x, t = threadIdx.x;
    const float* xb = base + (size_t)row * Hc;
    const float* db = delta + (size_t)row * Hc;
    float v[3];
    float s = 0.f, ss = 0.f;
#pragma unroll
    for (int i = 0; i < 3; i++) {
        float a = xb[t + i * 256] + db[t + i * 256];
        v[i] = a; s += a; ss += a * a;
    }
    __shared__ float rs[32], rss[32];
#pragma unroll
    for (int o = 16; o > 0; o >>= 1) {
        s  += __shfl_down_sync(0xffffffff, s, o);
        ss += __shfl_down_sync(0xffffffff, ss, o);
    }
    int wid = t >> 5, lane = t & 31;
    if (lane == 0) { rs[wid] = s; rss[wid] = ss; }
    __syncthreads();
    if (wid == 0) {
        s  = (lane < 8) ? rs[lane]  : 0.f;
        ss = (lane < 8) ? rss[lane] : 0.f;
#pragma unroll
        for (int o = 4; o > 0; o >>= 1) {
            s  += __shfl_down_sync(0xffffffff, s, o);
            ss += __shfl_down_sync(0xffffffff, ss, o);
        }
        if (lane == 0) { rs[0] = s; rss[0] = ss; }
    }
    __syncthreads();
    float mean = rs[0] * (1.f / Hc);
    float var  = rss[0] * (1.f / Hc) - mean * mean;
    float r = rsqrtf(var + EPSc);
#pragma unroll
    for (int i = 0; i < 3; i++) {
        int j = t + i * 256;
        out[(size_t)row * Hc + j] = (v[i] - mean) * r * sc[j] + bi[j];
    }
}

// ---------------- classifier + pooled output ----------------
__global__ __launch_bounds__(256) void cls_kernel(
    const float* __restrict__ x, const float* __restrict__ cw,
    const float* __restrict__ cb, float* __restrict__ out)
{
    int b = blockIdx.x, t = threadIdx.x;
    const float* p = x + (size_t)(b * Lwc) * Hc;
    for (int j = t; j < Hc; j += 256) out[Bc * NLABc + b * Hc + j] = p[j];
    int wid = t >> 5, lane = t & 31;
    if (wid < NLABc) {
        float s = 0.f;
        for (int j = lane; j < Hc; j += 32) s += p[j] * cw[wid * Hc + j];
#pragma unroll
        for (int o = 16; o > 0; o >>= 1) s += __shfl_down_sync(0xffffffff, s, o);
        if (lane == 0) out[b * NLABc + wid] = s + cb[wid];
    }
}

// ---------------- host ----------------
static float* symaddr(const void* sym) {
    void* p = nullptr;
    cudaGetSymbolAddress(&p, sym);
    return (float*)p;
}

extern "C" void kernel_launch(void* const* d_in, const int* in_sizes, int n_in,
                              void* d_out, int out_size)
{
    const float* hidden = (const float*)d_in[0];
    const int*   wti    = (const int*)  d_in[1];
    const int*   gmask  = (const int*)  d_in[2];
    const int*   wvalid = (const int*)  d_in[3];
    const float* qkv_w  = (const float*)d_in[4];
    const float* qkv_b  = (const float*)d_in[5];
    const float* out_w  = (const float*)d_in[6];
    const float* out_b  = (const float*)d_in[7];
    const float* ff1_w  = (const float*)d_in[8];
    const float* ff1_b  = (const float*)d_in[9];
    const float* ff2_w  = (const float*)d_in[10];
    const float* ff2_b  = (const float*)d_in[11];
    const float* ln1_s  = (const float*)d_in[12];
    const float* ln1_b  = (const float*)d_in[13];
    const float* ln2_s  = (const float*)d_in[14];
    const float* ln2_b  = (const float*)d_in[15];
    const float* cls_w  = (const float*)d_in[16];
    const float* cls_b  = (const float*)d_in[17];
    float* out = (float*)d_out;

    float* x   = symaddr(g_x);
    float* qkv = symaddr(g_qkv);
    float* ctx = symaddr(g_ctx);
    float* y   = symaddr(g_y);
    float* ff  = symaddr(g_ff);

    build_x_kernel<<<dim3(Lwc, Bc), 256>>>(hidden, wti, gmask, wvalid, x);

    const int MB = (Mc + BMt - 1) / BMt;     // 33
    dim3 gQKV(3 * Hc / BNt, MB);             // (18, 33)
    dim3 gH  (Hc / BNt,     MB);             // (6, 33)
    dim3 gFF (FFc / BNt,    MB);             // (16, 33)

    for (int l = 0; l < NLc; l++) {
        gemm_tf32_kernel<false><<<gQKV, 256>>>(x, qkv_w + (size_t)l * 3 * Hc * Hc,
                                               qkv_b + (size_t)l * 3 * Hc, qkv,
                                               Mc, 3 * Hc, Hc);
        attn_kernel<<<dim3(Lwc, NHc, Bc), 192>>>(qkv, wvalid, ctx);
        gemm_tf32_kernel<false><<<gH, 256>>>(ctx, out_w + (size_t)l * Hc * Hc,
                                             out_b + (size_t)l * Hc, y,
                                             Mc, Hc, Hc);
        add_ln_kernel<<<Mc, 256>>>(x, y, ln1_s + (size_t)l * Hc, ln1_b + (size_t)l * Hc, x);
        gemm_tf32_kernel<true><<<gFF, 256>>>(x, ff1_w + (size_t)l * FFc * Hc,
                                             ff1_b + (size_t)l * FFc, ff,
                                             Mc, FFc, Hc);
        gemm_tf32_kernel<false><<<gH, 256>>>(ff, ff2_w + (size_t)l * Hc * FFc,
                                             ff2_b + (size_t)l * Hc, y,
                                             Mc, Hc, FFc);
        add_ln_kernel<<<Mc, 256>>>(x, y, ln2_s + (size_t)l * Hc, ln2_b + (size_t)l * Hc, x);
    }

    cls_kernel<<<Bc, 256>>>(x, cls_w, cls_b, out);
}

// round 6
// speedup vs baseline: 7.1700x; 3.5225x over previous
#include <cuda_runtime.h>
#include <math.h>

// ---------------- problem constants ----------------
#define Bc    32
#define Sc    512
#define Hc    768
#define Wc    128
#define Gc    4
#define NHc   4
#define HDc   192
#define FFc   2048
#define NLc   2
#define NLABc 6
#define Lwc   (Wc + 1)          // 129
#define Mc    (Bc * Lwc)        // 4128
#define EPSc  1e-5f
#define SCALEc 0.07216878364870322f  // 1/sqrt(192)
#define ROW3H (3 * Hc)

// ---------------- scratch (device globals; no allocs) ----------------
__device__ float    g_x   [Mc * Hc];        // activations fp32 (for residual)
__device__ unsigned g_x_tf[Mc * Hc];        // activations tf32 (GEMM operand)
__device__ float    g_qkv [Mc * ROW3H];     // qkv fp32
__device__ unsigned g_ctx_tf[Mc * Hc];      // attention context (tf32, feeds proj GEMM)
__device__ float    g_y   [Mc * Hc];        // gemm out (proj / ff2)
__device__ unsigned g_ff_tf[Mc * FFc];      // ff1 output (tf32, feeds ff2 GEMM)
// preconverted tf32 weights
__device__ unsigned g_qkvw_tf[NLc * 3 * Hc * Hc];
__device__ unsigned g_outw_tf[NLc * Hc * Hc];
__device__ unsigned g_ff1w_tf[NLc * FFc * Hc];
__device__ unsigned g_ff2w_tf[NLc * Hc * FFc];

__device__ __forceinline__ unsigned f2tf(float f) {
    unsigned r;
    asm("cvt.rna.tf32.f32 %0, %1;" : "=r"(r) : "f"(f));
    return r;
}

// ---------------- weight preconversion (vectorized) ----------------
__global__ __launch_bounds__(256) void cvt_tf32_kernel(
    const float4* __restrict__ in, uint4* __restrict__ out, int n4)
{
    int i = blockIdx.x * blockDim.x + threadIdx.x;
    int stride = gridDim.x * blockDim.x;
    for (; i < n4; i += stride) {
        float4 v = in[i];
        uint4 o;
        o.x = f2tf(v.x); o.y = f2tf(v.y); o.z = f2tf(v.z); o.w = f2tf(v.w);
        out[i] = o;
    }
}

// ---------------- build x = [cls ; word embeddings] (fp32 + tf32) ----------------
__global__ __launch_bounds__(256) void build_x_kernel(
    const float* __restrict__ hidden, const int* __restrict__ wti,
    const int* __restrict__ gmask, const int* __restrict__ wvalid,
    float* __restrict__ x, unsigned* __restrict__ x_tf)
{
    int w = blockIdx.x, b = blockIdx.y, t = threadIdx.x;
    size_t ro = (size_t)(b * Lwc + w) * Hc;
    if (w == 0) {
        const float* hr = hidden + (size_t)(b * Sc) * Hc;
        for (int j = t; j < Hc; j += 256) { float v = hr[j]; x[ro + j] = v; x_tf[ro + j] = f2tf(v); }
        return;
    }
    int wi = w - 1;
    int valid = wvalid[b * Wc + wi];
    const float* hrows[Gc];
    float m[Gc];
    float cnt = 0.f;
#pragma unroll
    for (int g = 0; g < Gc; g++) {
        int idx = wti[(b * Wc + wi) * Gc + g];
        hrows[g] = hidden + (size_t)(b * Sc + idx) * Hc;
        m[g] = gmask[(b * Wc + wi) * Gc + g] ? 1.f : 0.f;
        cnt += m[g];
    }
    float inv = valid ? (1.f / fmaxf(cnt, 1.f)) : 0.f;
    for (int j = t; j < Hc; j += 256) {
        float s = 0.f;
#pragma unroll
        for (int g = 0; g < Gc; g++) s += m[g] * hrows[g][j];
        float v = s * inv;
        x[ro + j] = v; x_tf[ro + j] = f2tf(v);
    }
}

// =====================================================================
// TF32 tensor-core GEMM with cp.async 3-stage pipeline.
// C[M,N] = A[M,K] @ B[N,K]^T + bias.  A,B are preconverted tf32 bits.
// Tile 128x128x32, 256 threads, 8 warps (2x4), warp tile 64x32.
// Smem per stage: [128 rows][32 k] with 16B-chunk swizzle c' = c ^ (m&7).
// MODE 0: fp32 out.  MODE 1: relu + tf32 out.
// =====================================================================
#define BMt 128
#define BNt 128
#define BKt 32
#define STAGES 3
#define STAGE_BYTES 16384                  // 128*32*4
#define SB_OFF     (STAGES * STAGE_BYTES)  // B region byte offset

__device__ __forceinline__ void mma8(float* d, const unsigned* a, const unsigned* b) {
    asm volatile(
        "mma.sync.aligned.m16n8k8.row.col.f32.tf32.tf32.f32 "
        "{%0,%1,%2,%3}, {%4,%5,%6,%7}, {%8,%9}, {%0,%1,%2,%3};\n"
        : "+f"(d[0]), "+f"(d[1]), "+f"(d[2]), "+f"(d[3])
        : "r"(a[0]), "r"(a[1]), "r"(a[2]), "r"(a[3]),
          "r"(b[0]), "r"(b[1]));
}

__device__ __forceinline__ void cp16(unsigned dst, const void* src, unsigned sz) {
    asm volatile("cp.async.cg.shared.global [%0], [%1], 16, %2;\n"
                 :: "r"(dst), "l"(src), "r"(sz));
}

template <int MODE>
__global__ __launch_bounds__(256, 2) void gemm_tf32_async(
    const unsigned* __restrict__ A, const unsigned* __restrict__ B,
    const float* __restrict__ bias, void* __restrict__ Cout,
    int M, int N, int K)
{
    extern __shared__ unsigned gsm[];
    const unsigned sbase = (unsigned)__cvta_generic_to_shared(gsm);

    const int tid  = threadIdx.x;
    const int warp = tid >> 5;
    const int lane = tid & 31;
    const int wm = warp >> 2;       // 0..1
    const int wn = warp & 3;        // 0..3
    const int rowBase = blockIdx.y * BMt;
    const int colBase = blockIdx.x * BNt;
    const int fr = lane >> 2;       // 0..7
    const int fc = lane & 3;        // 0..3

    // copy setup: thread -> (row tm+32j, 16B chunk tc), j=0..3
    const int tm = tid >> 3;        // 0..31
    const int tc = tid & 7;         // 0..7
    const int cs16 = ((tc ^ (tm & 7)) << 4);   // swizzled byte offset in row
    const unsigned* aPtr[4];
    const unsigned* bPtr[4];
    unsigned aSz[4];
    unsigned dA[4], dB[4];
#pragma unroll
    for (int j = 0; j < 4; j++) {
        int m = tm + 32 * j;
        int grow = rowBase + m;
        aPtr[j] = A + (size_t)grow * K + 4 * tc;
        aSz[j]  = (grow < M) ? 16u : 0u;
        bPtr[j] = B + (size_t)(colBase + m) * K + 4 * tc;
        dA[j] = sbase + m * 128 + cs16;
        dB[j] = sbase + SB_OFF + m * 128 + cs16;
    }

    float acc[4][4][4];
#pragma unroll
    for (int i = 0; i < 4; i++)
#pragma unroll
        for (int j = 0; j < 4; j++)
#pragma unroll
            for (int q = 0; q < 4; q++) acc[i][j][q] = 0.f;

    const int nk = K / BKt;

    // prologue: issue stages 0 and 1
#pragma unroll
    for (int s = 0; s < 2; s++) {
        const int k0 = s * BKt;
        const unsigned so = s * STAGE_BYTES;
#pragma unroll
        for (int j = 0; j < 4; j++) cp16(dA[j] + so, aPtr[j] + k0, aSz[j]);
#pragma unroll
        for (int j = 0; j < 4; j++) cp16(dB[j] + so, bPtr[j] + k0, 16u);
        asm volatile("cp.async.commit_group;\n");
    }

    const int swz = fr << 2;
    for (int t = 0; t < nk; t++) {
        asm volatile("cp.async.wait_group 1;\n");
        __syncthreads();
        // issue stage t+2 (overwrites buffer of t-1; barrier above makes that safe)
        if (t + 2 < nk) {
            const int s = (t + 2) % STAGES;
            const int k0 = (t + 2) * BKt;
            const unsigned so = s * STAGE_BYTES;
#pragma unroll
            for (int j = 0; j < 4; j++) cp16(dA[j] + so, aPtr[j] + k0, aSz[j]);
#pragma unroll
            for (int j = 0; j < 4; j++) cp16(dB[j] + so, bPtr[j] + k0, 16u);
        }
        asm volatile("cp.async.commit_group;\n");

        // compute on stage t%3
        const unsigned* Ab = gsm + (t % STAGES) * (STAGE_BYTES / 4);
        const unsigned* Bb = gsm + SB_OFF / 4 + (t % STAGES) * (STAGE_BYTES / 4);
#pragma unroll
        for (int ks = 0; ks < 4; ks++) {
            const int kk = ks * 8;
            const int k1 = (kk + fc) ^ swz;
            const int k2 = (kk + fc + 4) ^ swz;
            unsigned af[4][4], bf[4][2];
#pragma unroll
            for (int mt = 0; mt < 4; mt++) {
                int m0 = wm * 64 + mt * 16 + fr;
                af[mt][0] = Ab[m0 * 32 + k1];
                af[mt][1] = Ab[(m0 + 8) * 32 + k1];
                af[mt][2] = Ab[m0 * 32 + k2];
                af[mt][3] = Ab[(m0 + 8) * 32 + k2];
            }
#pragma unroll
            for (int nt = 0; nt < 4; nt++) {
                int n0 = wn * 32 + nt * 8 + fr;
                bf[nt][0] = Bb[n0 * 32 + k1];
                bf[nt][1] = Bb[n0 * 32 + k2];
            }
#pragma unroll
            for (int mt = 0; mt < 4; mt++)
#pragma unroll
                for (int nt = 0; nt < 4; nt++)
                    mma8(acc[mt][nt], af[mt], bf[nt]);
        }
    }

    // ---- epilogue ----
#pragma unroll
    for (int mt = 0; mt < 4; mt++) {
        int row0 = rowBase + wm * 64 + mt * 16 + fr;
#pragma unroll
        for (int nt = 0; nt < 4; nt++) {
            int col = colBase + wn * 32 + nt * 8 + 2 * fc;
            float b0 = bias[col], b1 = bias[col + 1];
            float v0 = acc[mt][nt][0] + b0;
            float v1 = acc[mt][nt][1] + b1;
            float v2 = acc[mt][nt][2] + b0;
            float v3 = acc[mt][nt][3] + b1;
            if (MODE == 1) {
                v0 = fmaxf(v0, 0.f); v1 = fmaxf(v1, 0.f);
                v2 = fmaxf(v2, 0.f); v3 = fmaxf(v3, 0.f);
                unsigned* C = (unsigned*)Cout;
                if (row0 < M)
                    *(uint2*)(C + (size_t)row0 * N + col) = make_uint2(f2tf(v0), f2tf(v1));
                if (row0 + 8 < M)
                    *(uint2*)(C + (size_t)(row0 + 8) * N + col) = make_uint2(f2tf(v2), f2tf(v3));
            } else {
                float* C = (float*)Cout;
                if (row0 < M)
                    *(float2*)(C + (size_t)row0 * N + col) = make_float2(v0, v1);
                if (row0 + 8 < M)
                    *(float2*)(C + (size_t)(row0 + 8) * N + col) = make_float2(v2, v3);
            }
        }
    }
}

// =====================================================================
// attention: one block per (h, b). K and V staged in smem, q in batches of 8.
// =====================================================================
#define QB 8
#define KPAD 193
#define ATTN_SMEM_FLOATS (2 * Lwc * KPAD + QB * HDc + QB * 132 + 132 + QB)

__global__ __launch_bounds__(256) void attn_kernel(
    const float* __restrict__ qkv, const int* __restrict__ wvalid,
    unsigned* __restrict__ ctx_tf)
{
    extern __shared__ float sm[];
    float* sK = sm;                        // [Lwc][KPAD]
    float* sV = sK + Lwc * KPAD;           // [Lwc][KPAD]
    float* sQ = sV + Lwc * KPAD;           // [QB][HDc]
    float* sP = sQ + QB * HDc;             // [QB][132]
    float* sValid = sP + QB * 132;         // [132] additive bias 0 / -1e30
    float* sInv = sValid + 132;            // [QB]

    const int h = blockIdx.x, b = blockIdx.y, t = threadIdx.x;
    const float* kb = qkv + (size_t)b * Lwc * ROW3H + Hc + h * HDc;
    const float* vb = kb + Hc;
    const float* qb = qkv + (size_t)b * Lwc * ROW3H + h * HDc;

    for (int i = t; i < Lwc * HDc; i += 256) {
        int r = i / HDc, d = i - r * HDc;
        size_t go = (size_t)r * ROW3H + d;
        sK[r * KPAD + d] = kb[go];
        sV[r * KPAD + d] = vb[go];
    }
    for (int i = t; i < 132; i += 256)
        sValid[i] = (i == 0) ? 0.f : ((i < Lwc && wvalid[b * Wc + i - 1]) ? 0.f : -1e30f);
    __syncthreads();

    const int w = t >> 5, lane = t & 31;

    for (int q0 = 0; q0 < Lwc; q0 += QB) {
        const int nq = min(QB, Lwc - q0);
        // load Q batch (coalesced)
        for (int i = t; i < nq * HDc; i += 256) {
            int qi = i / HDc, d = i - qi * HDc;
            sQ[qi * HDc + d] = qb[(size_t)(q0 + qi) * ROW3H + d];
        }
        __syncthreads();
        // scores: thread t (<129) computes dot(q_qi, k_t) for qi<QB
        if (t < Lwc) {
            float a[QB];
#pragma unroll
            for (int qi = 0; qi < QB; qi++) a[qi] = 0.f;
            const float* kr = sK + t * KPAD;
            for (int d = 0; d < HDc; d++) {
                float kv = kr[d];
#pragma unroll
                for (int qi = 0; qi < QB; qi++) a[qi] += kv * sQ[qi * HDc + d];
            }
            float vbias = sValid[t];
#pragma unroll
            for (int qi = 0; qi < QB; qi++) sP[qi * 132 + t] = a[qi] * SCALEc + vbias;
        }
        __syncthreads();
        // softmax: warp w handles row w
        if (w < QB) {
            float* pr = sP + w * 132;
            float mx = -1e30f;
            for (int k = lane; k < Lwc; k += 32) mx = fmaxf(mx, pr[k]);
#pragma unroll
            for (int o = 16; o > 0; o >>= 1) mx = fmaxf(mx, __shfl_xor_sync(0xffffffffu, mx, o));
            float s = 0.f;
            for (int k = lane; k < Lwc; k += 32) { float e = __expf(pr[k] - mx); pr[k] = e; s += e; }
#pragma unroll
            for (int o = 16; o > 0; o >>= 1) s += __shfl_xor_sync(0xffffffffu, s, o);
            if (lane == 0) sInv[w] = 1.f / s;
        }
        __syncthreads();
        // AV: thread t (<192) handles dim d=t
        if (t < HDc) {
            float a[QB];
#pragma unroll
            for (int qi = 0; qi < QB; qi++) a[qi] = 0.f;
            for (int kk = 0; kk < Lwc; kk++) {
                float v = sV[kk * KPAD + t];
#pragma unroll
                for (int qi = 0; qi < QB; qi++) a[qi] += sP[qi * 132 + kk] * v;
            }
            for (int qi = 0; qi < nq; qi++)
                ctx_tf[(size_t)(b * Lwc + q0 + qi) * Hc + h * HDc + t] = f2tf(a[qi] * sInv[qi]);
        }
        __syncthreads();
    }
}

// ---------------- residual add + layernorm (fp32 + tf32 out) ----------------
__global__ __launch_bounds__(256) void add_ln_kernel(
    const float* __restrict__ base, const float* __restrict__ delta,
    const float* __restrict__ sc, const float* __restrict__ bi,
    float* __restrict__ out, unsigned* __restrict__ out_tf)
{
    int row = blockIdx.x, t = threadIdx.x;
    const float* xb = base + (size_t)row * Hc;
    const float* db = delta + (size_t)row * Hc;
    float v[3];
    float s = 0.f, ss = 0.f;
#pragma unroll
    for (int i = 0; i < 3; i++) {
        float a = xb[t + i * 256] + db[t + i * 256];
        v[i] = a; s += a; ss += a * a;
    }
    __shared__ float rs[32], rss[32];
#pragma unroll
    for (int o = 16; o > 0; o >>= 1) {
        s  += __shfl_down_sync(0xffffffffu, s, o);
        ss += __shfl_down_sync(0xffffffffu, ss, o);
    }
    int wid = t >> 5, lane = t & 31;
    if (lane == 0) { rs[wid] = s; rss[wid] = ss; }
    __syncthreads();
    if (wid == 0) {
        s  = (lane < 8) ? rs[lane]  : 0.f;
        ss = (lane < 8) ? rss[lane] : 0.f;
#pragma unroll
        for (int o = 4; o > 0; o >>= 1) {
            s  += __shfl_down_sync(0xffffffffu, s, o);
            ss += __shfl_down_sync(0xffffffffu, ss, o);
        }
        if (lane == 0) { rs[0] = s; rss[0] = ss; }
    }
    __syncthreads();
    float mean = rs[0] * (1.f / Hc);
    float var  = rss[0] * (1.f / Hc) - mean * mean;
    float r = rsqrtf(var + EPSc);
#pragma unroll
    for (int i = 0; i < 3; i++) {
        int j = t + i * 256;
        float o = (v[i] - mean) * r * sc[j] + bi[j];
        out[(size_t)row * Hc + j] = o;
        out_tf[(size_t)row * Hc + j] = f2tf(o);
    }
}

// ---------------- classifier + pooled output ----------------
__global__ __launch_bounds__(256) void cls_kernel(
    const float* __restrict__ x, const float* __restrict__ cw,
    const float* __restrict__ cb, float* __restrict__ out)
{
    int b = blockIdx.x, t = threadIdx.x;
    const float* p = x + (size_t)(b * Lwc) * Hc;
    for (int j = t; j < Hc; j += 256) out[Bc * NLABc + b * Hc + j] = p[j];
    int wid = t >> 5, lane = t & 31;
    if (wid < NLABc) {
        float s = 0.f;
        for (int j = lane; j < Hc; j += 32) s += p[j] * cw[wid * Hc + j];
#pragma unroll
        for (int o = 16; o > 0; o >>= 1) s += __shfl_down_sync(0xffffffffu, s, o);
        if (lane == 0) out[b * NLABc + wid] = s + cb[wid];
    }
}

// ---------------- host ----------------
template <typename T>
static T* symaddr(const void* sym) {
    void* p = nullptr;
    cudaGetSymbolAddress(&p, sym);
    return (T*)p;
}

extern "C" void kernel_launch(void* const* d_in, const int* in_sizes, int n_in,
                              void* d_out, int out_size)
{
    const float* hidden = (const float*)d_in[0];
    const int*   wti    = (const int*)  d_in[1];
    const int*   gmask  = (const int*)  d_in[2];
    const int*   wvalid = (const int*)  d_in[3];
    const float* qkv_w  = (const float*)d_in[4];
    const float* qkv_b  = (const float*)d_in[5];
    const float* out_w  = (const float*)d_in[6];
    const float* out_b  = (const float*)d_in[7];
    const float* ff1_w  = (const float*)d_in[8];
    const float* ff1_b  = (const float*)d_in[9];
    const float* ff2_w  = (const float*)d_in[10];
    const float* ff2_b  = (const float*)d_in[11];
    const float* ln1_s  = (const float*)d_in[12];
    const float* ln1_b  = (const float*)d_in[13];
    const float* ln2_s  = (const float*)d_in[14];
    const float* ln2_b  = (const float*)d_in[15];
    const float* cls_w  = (const float*)d_in[16];
    const float* cls_b  = (const float*)d_in[17];
    float* out = (float*)d_out;

    float*    x      = symaddr<float>(g_x);
    unsigned* x_tf   = symaddr<unsigned>(g_x_tf);
    float*    qkv    = symaddr<float>(g_qkv);
    unsigned* ctx_tf = symaddr<unsigned>(g_ctx_tf);
    float*    y      = symaddr<float>(g_y);
    unsigned* ff_tf  = symaddr<unsigned>(g_ff_tf);
    unsigned* qkvw_tf = symaddr<unsigned>(g_qkvw_tf);
    unsigned* outw_tf = symaddr<unsigned>(g_outw_tf);
    unsigned* ff1w_tf = symaddr<unsigned>(g_ff1w_tf);
    unsigned* ff2w_tf = symaddr<unsigned>(g_ff2w_tf);

    // opt-in large smem (host-side attribute set; not a graph op)
    static bool attr_done = false;
    if (!attr_done) {
        cudaFuncSetAttribute(gemm_tf32_async<0>, cudaFuncAttributeMaxDynamicSharedMemorySize,
                             STAGES * STAGE_BYTES * 2);
        cudaFuncSetAttribute(gemm_tf32_async<1>, cudaFuncAttributeMaxDynamicSharedMemorySize,
                             STAGES * STAGE_BYTES * 2);
        cudaFuncSetAttribute(attn_kernel, cudaFuncAttributeMaxDynamicSharedMemorySize,
                             ATTN_SMEM_FLOATS * 4);
        attr_done = true;
    }
    const unsigned gemmSmem = STAGES * STAGE_BYTES * 2;
    const unsigned attnSmem = ATTN_SMEM_FLOATS * 4;

    // weight preconversion (runs every call; deterministic)
    cvt_tf32_kernel<<<256, 256>>>((const float4*)qkv_w, (uint4*)qkvw_tf, NLc * 3 * Hc * Hc / 4);
    cvt_tf32_kernel<<<128, 256>>>((const float4*)out_w, (uint4*)outw_tf, NLc * Hc * Hc / 4);
    cvt_tf32_kernel<<<256, 256>>>((const float4*)ff1_w, (uint4*)ff1w_tf, NLc * FFc * Hc / 4);
    cvt_tf32_kernel<<<256, 256>>>((const float4*)ff2_w, (uint4*)ff2w_tf, NLc * Hc * FFc / 4);

    build_x_kernel<<<dim3(Lwc, Bc), 256>>>(hidden, wti, gmask, wvalid, x, x_tf);

    const int MB = (Mc + BMt - 1) / BMt;     // 33
    dim3 gQKV(3 * Hc / BNt, MB);             // (18, 33)
    dim3 gH  (Hc / BNt,     MB);             // (6, 33)
    dim3 gFF (FFc / BNt,    MB);             // (16, 33)

    for (int l = 0; l < NLc; l++) {
        gemm_tf32_async<0><<<gQKV, 256, gemmSmem>>>(
            x_tf, qkvw_tf + (size_t)l * 3 * Hc * Hc,
            qkv_b + (size_t)l * 3 * Hc, qkv, Mc, 3 * Hc, Hc);
        attn_kernel<<<dim3(NHc, Bc), 256, attnSmem>>>(qkv, wvalid, ctx_tf);
        gemm_tf32_async<0><<<gH, 256, gemmSmem>>>(
            ctx_tf, outw_tf + (size_t)l * Hc * Hc,
            out_b + (size_t)l * Hc, y, Mc, Hc, Hc);
        add_ln_kernel<<<Mc, 256>>>(x, y, ln1_s + (size_t)l * Hc, ln1_b + (size_t)l * Hc, x, x_tf);
        gemm_tf32_async<1><<<gFF, 256, gemmSmem>>>(
            x_tf, ff1w_tf + (size_t)l * FFc * Hc,
            ff1_b + (size_t)l * FFc, ff_tf, Mc, FFc, Hc);
        gemm_tf32_async<0><<<gH, 256, gemmSmem>>>(
            ff_tf, ff2w_tf + (size_t)l * Hc * FFc,
            ff2_b + (size_t)l * Hc, y, Mc, Hc, FFc);
        add_ln_kernel<<<Mc, 256>>>(x, y, ln2_s + (size_t)l * Hc, ln2_b + (size_t)l * Hc, x, x_tf);
    }

    cls_kernel<<<Bc, 256>>>(x, cls_w, cls_b, out);
}

// round 8
// speedup vs baseline: 9.6375x; 1.3442x over previous
#include <cuda_runtime.h>
#include <cuda_fp16.h>
#include <math.h>

// ---------------- problem constants ----------------
#define Bc    32
#define Sc    512
#define Hc    768
#define Wc    128
#define Gc    4
#define NHc   4
#define HDc   192
#define FFc   2048
#define NLc   2
#define NLABc 6
#define Lwc   (Wc + 1)          // 129
#define Mc    (Bc * Lwc)        // 4128
#define EPSc  1e-5f
#define SCALEc 0.07216878364870322f  // 1/sqrt(192)
#define ROW3H (3 * Hc)

// ---------------- scratch (device globals; no allocs) ----------------
__device__ float  g_x   [Mc * Hc];        // activations fp32 (residual path)
__device__ __half g_x_h [Mc * Hc];        // activations fp16 (GEMM operand)
__device__ float  g_qkv [Mc * ROW3H];     // qkv fp32 (attention reads fp32)
__device__ __half g_ctx_h[Mc * Hc];       // attention context fp16
__device__ float  g_y   [Mc * Hc];        // gemm out (proj / ff2) fp32
__device__ __half g_ff_h[Mc * FFc];       // ff1 output fp16
// preconverted fp16 weights
__device__ __half g_qkvw_h[NLc * 3 * Hc * Hc];
__device__ __half g_outw_h[NLc * Hc * Hc];
__device__ __half g_ff1w_h[NLc * FFc * Hc];
__device__ __half g_ff2w_h[NLc * Hc * FFc];

// ---------------- merged weight conversion (8 floats/item) ----------------
#define CVN1 442368   // 2*3*768*768/8
#define CVN2 147456   // 2*768*768/8
#define CVN3 393216   // 2*2048*768/8
#define CVN4 393216
#define CVT_TOT (CVN1 + CVN2 + CVN3 + CVN4)   // 1376256

__global__ __launch_bounds__(256) void cvt_all_kernel(
    const float4* __restrict__ w1, const float4* __restrict__ w2,
    const float4* __restrict__ w3, const float4* __restrict__ w4,
    uint4* __restrict__ o1, uint4* __restrict__ o2,
    uint4* __restrict__ o3, uint4* __restrict__ o4)
{
    int i = blockIdx.x * blockDim.x + threadIdx.x;
    int stride = gridDim.x * blockDim.x;
    for (; i < CVT_TOT; i += stride) {
        const float4* src; uint4* dst; int j;
        if (i < CVN1)                 { src = w1; dst = o1; j = i; }
        else if (i < CVN1 + CVN2)     { src = w2; dst = o2; j = i - CVN1; }
        else if (i < CVN1 + CVN2 + CVN3) { src = w3; dst = o3; j = i - CVN1 - CVN2; }
        else                          { src = w4; dst = o4; j = i - CVN1 - CVN2 - CVN3; }
        float4 a = src[2 * j], b = src[2 * j + 1];
        __half2 h0 = __floats2half2_rn(a.x, a.y);
        __half2 h1 = __floats2half2_rn(a.z, a.w);
        __half2 h2 = __floats2half2_rn(b.x, b.y);
        __half2 h3 = __floats2half2_rn(b.z, b.w);
        uint4 o;
        o.x = *(unsigned*)&h0; o.y = *(unsigned*)&h1;
        o.z = *(unsigned*)&h2; o.w = *(unsigned*)&h3;
        dst[j] = o;
    }
}

// ---------------- build x = [cls ; word embeddings] ----------------
__global__ __launch_bounds__(256) void build_x_kernel(
    const float* __restrict__ hidden, const int* __restrict__ wti,
    const int* __restrict__ gmask, const int* __restrict__ wvalid,
    float* __restrict__ x, __half* __restrict__ x_h)
{
    int w = blockIdx.x, b = blockIdx.y, t = threadIdx.x;
    size_t ro = (size_t)(b * Lwc + w) * Hc;
    if (w == 0) {
        const float* hr = hidden + (size_t)(b * Sc) * Hc;
        for (int j = t; j < Hc; j += 256) {
            float v = hr[j]; x[ro + j] = v; x_h[ro + j] = __float2half_rn(v);
        }
        return;
    }
    int wi = w - 1;
    int valid = wvalid[b * Wc + wi];
    const float* hrows[Gc];
    float m[Gc];
    float cnt = 0.f;
#pragma unroll
    for (int g = 0; g < Gc; g++) {
        int idx = wti[(b * Wc + wi) * Gc + g];
        hrows[g] = hidden + (size_t)(b * Sc + idx) * Hc;
        m[g] = gmask[(b * Wc + wi) * Gc + g] ? 1.f : 0.f;
        cnt += m[g];
    }
    float inv = valid ? (1.f / fmaxf(cnt, 1.f)) : 0.f;
    for (int j = t; j < Hc; j += 256) {
        float s = 0.f;
#pragma unroll
        for (int g = 0; g < Gc; g++) s += m[g] * hrows[g][j];
        float v = s * inv;
        x[ro + j] = v; x_h[ro + j] = __float2half_rn(v);
    }
}

// =====================================================================
// FP16 tensor-core GEMM, cp.async 3-stage pipeline, ldmatrix fragments.
// C[M,N] = A[M,K] @ B[N,K]^T + bias.  A,B fp16, accumulate fp32.
// Tile 128x128x64, 256 threads, 8 warps (2x4), warp tile 64x32.
// Smem per operand stage: [128 rows][64 halves = 128B], SW128 swizzle
//   chunk' = chunk ^ (row & 7).
// MODE 0: fp32 out.  MODE 1: relu + fp16 out.
// =====================================================================
#define BMt 128
#define BNt 128
#define BKt 64
#define STAGES 3
#define SA_BYTES 16384                    // 128 * 128B
#define SB_OFF   (STAGES * SA_BYTES)      // 49152
#define GEMM_SMEM (2 * STAGES * SA_BYTES) // 98304

__device__ __forceinline__ void ldm4(unsigned* r, unsigned addr) {
    asm volatile("ldmatrix.sync.aligned.m8n8.x4.shared.b16 {%0,%1,%2,%3}, [%4];"
                 : "=r"(r[0]), "=r"(r[1]), "=r"(r[2]), "=r"(r[3]) : "r"(addr));
}

__device__ __forceinline__ void mma16(float* d, const unsigned* a, unsigned b0, unsigned b1) {
    asm volatile(
        "mma.sync.aligned.m16n8k16.row.col.f32.f16.f16.f32 "
        "{%0,%1,%2,%3}, {%4,%5,%6,%7}, {%8,%9}, {%0,%1,%2,%3};\n"
        : "+f"(d[0]), "+f"(d[1]), "+f"(d[2]), "+f"(d[3])
        : "r"(a[0]), "r"(a[1]), "r"(a[2]), "r"(a[3]), "r"(b0), "r"(b1));
}

__device__ __forceinline__ void cp16(unsigned dst, const void* src, unsigned sz) {
    asm volatile("cp.async.cg.shared.global [%0], [%1], 16, %2;\n"
                 :: "r"(dst), "l"(src), "r"(sz));
}

template <int MODE>
__global__ __launch_bounds__(256, 2) void gemm_f16_async(
    const __half* __restrict__ A, const __half* __restrict__ B,
    const float* __restrict__ bias, void* __restrict__ Cout,
    int M, int N, int K)
{
    extern __shared__ char gsm[];
    const unsigned sbase = (unsigned)__cvta_generic_to_shared(gsm);

    const int tid  = threadIdx.x;
    const int warp = tid >> 5;
    const int lane = tid & 31;
    const int wm = warp >> 2;       // 0..1
    const int wn = warp & 3;        // 0..3
    const int rowBase = blockIdx.y * BMt;
    const int colBase = blockIdx.x * BNt;

    // ---- copy mapping: thread -> (row cr+32j, chunk cc) ----
    const int cc = tid & 7;         // 16B chunk within 128B row
    const int cr = tid >> 3;        // 0..31
    const __half* aSrc[4];
    const __half* bSrc[4];
    unsigned aSz[4];
    unsigned dA[4], dB[4];
#pragma unroll
    for (int j = 0; j < 4; j++) {
        int r = cr + 32 * j;
        int grow = rowBase + r;
        aSrc[j] = A + (size_t)grow * K + cc * 8;
        aSz[j]  = (grow < M) ? 16u : 0u;
        bSrc[j] = B + (size_t)(colBase + r) * K + cc * 8;
        unsigned d = r * 128 + ((cc ^ (r & 7)) << 4);
        dA[j] = sbase + d;
        dB[j] = sbase + SB_OFF + d;
    }

    // ---- ldmatrix fragment addressing (per-lane constants) ----
    const int wr     = lane & 7;            // row within 8-row matrix
    const int rowOff = ((lane >> 3) & 1) * 8 + wr;
    const int cAdd   = lane >> 4;           // 0: k0-7 chunk, 1: k8-15 chunk
    const unsigned aFragBase = (wm * 64 + rowOff) * 128;
    const unsigned bFragBase = SB_OFF + (wn * 32 + rowOff) * 128;
    unsigned swz[4];
#pragma unroll
    for (int ks = 0; ks < 4; ks++)
        swz[ks] = ((unsigned)((2 * ks + cAdd) ^ wr)) << 4;

    float acc[4][4][4];
#pragma unroll
    for (int i = 0; i < 4; i++)
#pragma unroll
        for (int j = 0; j < 4; j++)
#pragma unroll
            for (int q = 0; q < 4; q++) acc[i][j][q] = 0.f;

    const int nk = K / BKt;

    // ---- prologue: issue stages 0,1 ----
#pragma unroll
    for (int s = 0; s < 2; s++) {
        const int k0 = s * BKt;
        const unsigned so = s * SA_BYTES;
#pragma unroll
        for (int j = 0; j < 4; j++) cp16(dA[j] + so, aSrc[j] + k0, aSz[j]);
#pragma unroll
        for (int j = 0; j < 4; j++) cp16(dB[j] + so, bSrc[j] + k0, 16u);
        asm volatile("cp.async.commit_group;\n");
    }

    for (int t = 0; t < nk; t++) {
        asm volatile("cp.async.wait_group 1;\n");
        __syncthreads();
        if (t + 2 < nk) {
            const int s = (t + 2) % STAGES;
            const int k0 = (t + 2) * BKt;
            const unsigned so = s * SA_BYTES;
#pragma unroll
            for (int j = 0; j < 4; j++) cp16(dA[j] + so, aSrc[j] + k0, aSz[j]);
#pragma unroll
            for (int j = 0; j < 4; j++) cp16(dB[j] + so, bSrc[j] + k0, 16u);
        }
        asm volatile("cp.async.commit_group;\n");

        const unsigned stOff = (t % STAGES) * SA_BYTES;
#pragma unroll
        for (int ks = 0; ks < 4; ks++) {
            const unsigned so = swz[ks] + stOff;
            unsigned af[4][4];
#pragma unroll
            for (int mt = 0; mt < 4; mt++)
                ldm4(af[mt], sbase + aFragBase + mt * 2048 + so);
            unsigned bf[2][4];
#pragma unroll
            for (int ntp = 0; ntp < 2; ntp++)
                ldm4(bf[ntp], sbase + bFragBase + ntp * 2048 + so);
#pragma unroll
            for (int mt = 0; mt < 4; mt++)
#pragma unroll
                for (int ntp = 0; ntp < 2; ntp++)
#pragma unroll
                    for (int ntl = 0; ntl < 2; ntl++)
                        mma16(acc[mt][ntp * 2 + ntl], af[mt],
                              bf[ntp][ntl], bf[ntp][2 + ntl]);
        }
    }

    // ---- epilogue ----
    const int fr = lane >> 2;   // 0..7
    const int fc = lane & 3;    // 0..3
#pragma unroll
    for (int mt = 0; mt < 4; mt++) {
        int row0 = rowBase + wm * 64 + mt * 16 + fr;
#pragma unroll
        for (int nt = 0; nt < 4; nt++) {
            int col = colBase + wn * 32 + nt * 8 + 2 * fc;
            float b0 = bias[col], b1 = bias[col + 1];
            float v0 = acc[mt][nt][0] + b0;
            float v1 = acc[mt][nt][1] + b1;
            float v2 = acc[mt][nt][2] + b0;
            float v3 = acc[mt][nt][3] + b1;
            if (MODE == 1) {
                v0 = fmaxf(v0, 0.f); v1 = fmaxf(v1, 0.f);
                v2 = fmaxf(v2, 0.f); v3 = fmaxf(v3, 0.f);
                __half2* C = (__half2*)Cout;
                if (row0 < M)
                    C[((size_t)row0 * N + col) >> 1] = __floats2half2_rn(v0, v1);
                if (row0 + 8 < M)
                    C[((size_t)(row0 + 8) * N + col) >> 1] = __floats2half2_rn(v2, v3);
            } else {
                float* C = (float*)Cout;
                if (row0 < M)
                    *(float2*)(C + (size_t)row0 * N + col) = make_float2(v0, v1);
                if (row0 + 8 < M)
                    *(float2*)(C + (size_t)(row0 + 8) * N + col) = make_float2(v2, v3);
            }
        }
    }
}

// =====================================================================
// attention: one block per (h, b). K and V staged in smem, q in batches of 8.
// =====================================================================
#define QB 8
#define KPAD 193
#define ATTN_SMEM_FLOATS (2 * Lwc * KPAD + QB * HDc + QB * 132 + 132 + QB)

__global__ __launch_bounds__(256) void attn_kernel(
    const float* __restrict__ qkv, const int* __restrict__ wvalid,
    __half* __restrict__ ctx_h)
{
    extern __shared__ float sm[];
    float* sK = sm;                        // [Lwc][KPAD]
    float* sV = sK + Lwc * KPAD;           // [Lwc][KPAD]
    float* sQ = sV + Lwc * KPAD;           // [QB][HDc]
    float* sP = sQ + QB * HDc;             // [QB][132]
    float* sValid = sP + QB * 132;         // [132]
    float* sInv = sValid + 132;            // [QB]

    const int h = blockIdx.x, b = blockIdx.y, t = threadIdx.x;
    const float* kb = qkv + (size_t)b * Lwc * ROW3H + Hc + h * HDc;
    const float* vb = kb + Hc;
    const float* qb = qkv + (size_t)b * Lwc * ROW3H + h * HDc;

    for (int i = t; i < Lwc * HDc; i += 256) {
        int r = i / HDc, d = i - r * HDc;
        size_t go = (size_t)r * ROW3H + d;
        sK[r * KPAD + d] = kb[go];
        sV[r * KPAD + d] = vb[go];
    }
    for (int i = t; i < 132; i += 256)
        sValid[i] = (i == 0) ? 0.f : ((i < Lwc && wvalid[b * Wc + i - 1]) ? 0.f : -1e30f);
    __syncthreads();

    const int w = t >> 5, lane = t & 31;

    for (int q0 = 0; q0 < Lwc; q0 += QB) {
        const int nq = min(QB, Lwc - q0);
        for (int i = t; i < nq * HDc; i += 256) {
            int qi = i / HDc, d = i - qi * HDc;
            sQ[qi * HDc + d] = qb[(size_t)(q0 + qi) * ROW3H + d];
        }
        __syncthreads();
        if (t < Lwc) {
            float a[QB];
#pragma unroll
            for (int qi = 0; qi < QB; qi++) a[qi] = 0.f;
            const float* kr = sK + t * KPAD;
            for (int d = 0; d < HDc; d++) {
                float kv = kr[d];
#pragma unroll
                for (int qi = 0; qi < QB; qi++) a[qi] += kv * sQ[qi * HDc + d];
            }
            float vbias = sValid[t];
#pragma unroll
            for (int qi = 0; qi < QB; qi++) sP[qi * 132 + t] = a[qi] * SCALEc + vbias;
        }
        __syncthreads();
        if (w < QB) {
            float* pr = sP + w * 132;
            float mx = -1e30f;
            for (int k = lane; k < Lwc; k += 32) mx = fmaxf(mx, pr[k]);
#pragma unroll
            for (int o = 16; o > 0; o >>= 1) mx = fmaxf(mx, __shfl_xor_sync(0xffffffffu, mx, o));
            float s = 0.f;
            for (int k = lane; k < Lwc; k += 32) { float e = __expf(pr[k] - mx); pr[k] = e; s += e; }
#pragma unroll
            for (int o = 16; o > 0; o >>= 1) s += __shfl_xor_sync(0xffffffffu, s, o);
            if (lane == 0) sInv[w] = 1.f / s;
        }
        __syncthreads();
        if (t < HDc) {
            float a[QB];
#pragma unroll
            for (int qi = 0; qi < QB; qi++) a[qi] = 0.f;
            for (int kk = 0; kk < Lwc; kk++) {
                float v = sV[kk * KPAD + t];
#pragma unroll
                for (int qi = 0; qi < QB; qi++) a[qi] += sP[qi * 132 + kk] * v;
            }
            for (int qi = 0; qi < nq; qi++)
                ctx_h[(size_t)(b * Lwc + q0 + qi) * Hc + h * HDc + t] =
                    __float2half_rn(a[qi] * sInv[qi]);
        }
        __syncthreads();
    }
}

// ---------------- residual add + layernorm (fp32 + fp16 out) ----------------
__global__ __launch_bounds__(256) void add_ln_kernel(
    const float* __restrict__ base, const float* __restrict__ delta,
    const float* __restrict__ sc, const float* __restrict__ bi,
    float* __restrict__ out, __half* __restrict__ out_h)
{
    int row = blockIdx.x, t = threadIdx.x;
    const float* xb = base + (size_t)row * Hc;
    const float* db = delta + (size_t)row * Hc;
    float v[3];
    float s = 0.f, ss = 0.f;
#pragma unroll
    for (int i = 0; i < 3; i++) {
        float a = xb[t + i * 256] + db[t + i * 256];
        v[i] = a; s += a; ss += a * a;
    }
    __shared__ float rs[32], rss[32];
#pragma unroll
    for (int o = 16; o > 0; o >>= 1) {
        s  += __shfl_down_sync(0xffffffffu, s, o);
        ss += __shfl_down_sync(0xffffffffu, ss, o);
    }
    int wid = t >> 5, lane = t & 31;
    if (lane == 0) { rs[wid] = s; rss[wid] = ss; }
    __syncthreads();
    if (wid == 0) {
        s  = (lane < 8) ? rs[lane]  : 0.f;
        ss = (lane < 8) ? rss[lane] : 0.f;
#pragma unroll
        for (int o = 4; o > 0; o >>= 1) {
            s  += __shfl_down_sync(0xffffffffu, s, o);
            ss += __shfl_down_sync(0xffffffffu, ss, o);
        }
        if (lane == 0) { rs[0] = s; rss[0] = ss; }
    }
    __syncthreads();
    float mean = rs[0] * (1.f / Hc);
    float var  = rss[0] * (1.f / Hc) - mean * mean;
    float r = rsqrtf(var + EPSc);
#pragma unroll
    for (int i = 0; i < 3; i++) {
        int j = t + i * 256;
        float o = (v[i] - mean) * r * sc[j] + bi[j];
        out[(size_t)row * Hc + j] = o;
        out_h[(size_t)row * Hc + j] = __float2half_rn(o);
    }
}

// ---------------- classifier + pooled output ----------------
__global__ __launch_bounds__(256) void cls_kernel(
    const float* __restrict__ x, const float* __restrict__ cw,
    const float* __restrict__ cb, float* __restrict__ out)
{
    int b = blockIdx.x, t = threadIdx.x;
    const float* p = x + (size_t)(b * Lwc) * Hc;
    for (int j = t; j < Hc; j += 256) out[Bc * NLABc + b * Hc + j] = p[j];
    int wid = t >> 5, lane = t & 31;
    if (wid < NLABc) {
        float s = 0.f;
        for (int j = lane; j < Hc; j += 32) s += p[j] * cw[wid * Hc + j];
#pragma unroll
        for (int o = 16; o > 0; o >>= 1) s += __shfl_down_sync(0xffffffffu, s, o);
        if (lane == 0) out[b * NLABc + wid] = s + cb[wid];
    }
}

// ---------------- host ----------------
template <typename T>
static T* symaddr(const void* sym) {
    void* p = nullptr;
    cudaGetSymbolAddress(&p, sym);
    return (T*)p;
}

extern "C" void kernel_launch(void* const* d_in, const int* in_sizes, int n_in,
                              void* d_out, int out_size)
{
    const float* hidden = (const float*)d_in[0];
    const int*   wti    = (const int*)  d_in[1];
    const int*   gmask  = (const int*)  d_in[2];
    const int*   wvalid = (const int*)  d_in[3];
    const float* qkv_w  = (const float*)d_in[4];
    const float* qkv_b  = (const float*)d_in[5];
    const float* out_w  = (const float*)d_in[6];
    const float* out_b  = (const float*)d_in[7];
    const float* ff1_w  = (const float*)d_in[8];
    const float* ff1_b  = (const float*)d_in[9];
    const float* ff2_w  = (const float*)d_in[10];
    const float* ff2_b  = (const float*)d_in[11];
    const float* ln1_s  = (const float*)d_in[12];
    const float* ln1_b  = (const float*)d_in[13];
    const float* ln2_s  = (const float*)d_in[14];
    const float* ln2_b  = (const float*)d_in[15];
    const float* cls_w  = (const float*)d_in[16];
    const float* cls_b  = (const float*)d_in[17];
    float* out = (float*)d_out;

    float*  x     = symaddr<float>(g_x);
    __half* x_h   = symaddr<__half>(g_x_h);
    float*  qkv   = symaddr<float>(g_qkv);
    __half* ctx_h = symaddr<__half>(g_ctx_h);
    float*  y     = symaddr<float>(g_y);
    __half* ff_h  = symaddr<__half>(g_ff_h);
    __half* qkvw_h = symaddr<__half>(g_qkvw_h);
    __half* outw_h = symaddr<__half>(g_outw_h);
    __half* ff1w_h = symaddr<__half>(g_ff1w_h);
    __half* ff2w_h = symaddr<__half>(g_ff2w_h);

    static bool attr_done = false;
    if (!attr_done) {
        cudaFuncSetAttribute(gemm_f16_async<0>, cudaFuncAttributeMaxDynamicSharedMemorySize,
                             GEMM_SMEM);
        cudaFuncSetAttribute(gemm_f16_async<1>, cudaFuncAttributeMaxDynamicSharedMemorySize,
                             GEMM_SMEM);
        cudaFuncSetAttribute(attn_kernel, cudaFuncAttributeMaxDynamicSharedMemorySize,
                             ATTN_SMEM_FLOATS * 4);
        attr_done = true;
    }
    const unsigned attnSmem = ATTN_SMEM_FLOATS * 4;

    cvt_all_kernel<<<256, 256>>>(
        (const float4*)qkv_w, (const float4*)out_w,
        (const float4*)ff1_w, (const float4*)ff2_w,
        (uint4*)qkvw_h, (uint4*)outw_h, (uint4*)ff1w_h, (uint4*)ff2w_h);

    build_x_kernel<<<dim3(Lwc, Bc), 256>>>(hidden, wti, gmask, wvalid, x, x_h);

    const int MB = (Mc + BMt - 1) / BMt;     // 33
    dim3 gQKV(3 * Hc / BNt, MB);             // (18, 33)
    dim3 gH  (Hc / BNt,     MB);             // (6, 33)
    dim3 gFF (FFc / BNt,    MB);             // (16, 33)

    for (int l = 0; l < NLc; l++) {
        gemm_f16_async<0><<<gQKV, 256, GEMM_SMEM>>>(
            x_h, qkvw_h + (size_t)l * 3 * Hc * Hc,
            qkv_b + (size_t)l * 3 * Hc, qkv, Mc, 3 * Hc, Hc);
        attn_kernel<<<dim3(NHc, Bc), 256, attnSmem>>>(qkv, wvalid, ctx_h);
        gemm_f16_async<0><<<gH, 256, GEMM_SMEM>>>(
            ctx_h, outw_h + (size_t)l * Hc * Hc,
            out_b + (size_t)l * Hc, y, Mc, Hc, Hc);
        add_ln_kernel<<<Mc, 256>>>(x, y, ln1_s + (size_t)l * Hc, ln1_b + (size_t)l * Hc, x, x_h);
        gemm_f16_async<1><<<gFF, 256, GEMM_SMEM>>>(
            x_h, ff1w_h + (size_t)l * FFc * Hc,
            ff1_b + (size_t)l * FFc, ff_h, Mc, FFc, Hc);
        gemm_f16_async<0><<<gH, 256, GEMM_SMEM>>>(
            ff_h, ff2w_h + (size_t)l * Hc * FFc,
            ff2_b + (size_t)l * Hc, y, Mc, Hc, FFc);
        add_ln_kernel<<<Mc, 256>>>(x, y, ln2_s + (size_t)l * Hc, ln2_b + (size_t)l * Hc, x, x_h);
    }

    cls_kernel<<<Bc, 256>>>(x, cls_w, cls_b, out);
}

// round 10
// speedup vs baseline: 15.0708x; 1.5638x over previous
#include <cuda_runtime.h>
#include <cuda_fp16.h>
#include <math.h>

// ---------------- problem constants ----------------
#define Bc    32
#define Sc    512
#define Hc    768
#define Wc    128
#define Gc    4
#define NHc   4
#define HDc   192
#define FFc   2048
#define NLc   2
#define NLABc 6
#define Lwc   (Wc + 1)          // 129
#define Mc    (Bc * Lwc)        // 4128
#define EPSc  1e-5f
#define SCALEc 0.07216878364870322f  // 1/sqrt(192)
#define ROW3H (3 * Hc)

// ---------------- scratch (device globals; no allocs) ----------------
__device__ float  g_x   [Mc * Hc];
__device__ __half g_x_h [Mc * Hc];
__device__ float  g_qkv [Mc * ROW3H];
__device__ __half g_ctx_h[Mc * Hc];
__device__ float  g_y   [Mc * Hc];
__device__ __half g_ff_h[Mc * FFc];
__device__ __half g_qkvw_h[NLc * 3 * Hc * Hc];
__device__ __half g_outw_h[NLc * Hc * Hc];
__device__ __half g_ff1w_h[NLc * FFc * Hc];
__device__ __half g_ff2w_h[NLc * Hc * FFc];

// ---------------- merged weight conversion ----------------
#define CVN1 442368
#define CVN2 147456
#define CVN3 393216
#define CVN4 393216
#define CVT_TOT (CVN1 + CVN2 + CVN3 + CVN4)

__global__ __launch_bounds__(256) void cvt_all_kernel(
    const float4* __restrict__ w1, const float4* __restrict__ w2,
    const float4* __restrict__ w3, const float4* __restrict__ w4,
    uint4* __restrict__ o1, uint4* __restrict__ o2,
    uint4* __restrict__ o3, uint4* __restrict__ o4)
{
    int i = blockIdx.x * blockDim.x + threadIdx.x;
    int stride = gridDim.x * blockDim.x;
    for (; i < CVT_TOT; i += stride) {
        const float4* src; uint4* dst; int j;
        if (i < CVN1)                 { src = w1; dst = o1; j = i; }
        else if (i < CVN1 + CVN2)     { src = w2; dst = o2; j = i - CVN1; }
        else if (i < CVN1 + CVN2 + CVN3) { src = w3; dst = o3; j = i - CVN1 - CVN2; }
        else                          { src = w4; dst = o4; j = i - CVN1 - CVN2 - CVN3; }
        float4 a = src[2 * j], b = src[2 * j + 1];
        __half2 h0 = __floats2half2_rn(a.x, a.y);
        __half2 h1 = __floats2half2_rn(a.z, a.w);
        __half2 h2 = __floats2half2_rn(b.x, b.y);
        __half2 h3 = __floats2half2_rn(b.z, b.w);
        uint4 o;
        o.x = *(unsigned*)&h0; o.y = *(unsigned*)&h1;
        o.z = *(unsigned*)&h2; o.w = *(unsigned*)&h3;
        dst[j] = o;
    }
}

// ---------------- build x ----------------
__global__ __launch_bounds__(256) void build_x_kernel(
    const float* __restrict__ hidden, const int* __restrict__ wti,
    const int* __restrict__ gmask, const int* __restrict__ wvalid,
    float* __restrict__ x, __half* __restrict__ x_h)
{
    int w = blockIdx.x, b = blockIdx.y, t = threadIdx.x;
    size_t ro = (size_t)(b * Lwc + w) * Hc;
    if (w == 0) {
        const float* hr = hidden + (size_t)(b * Sc) * Hc;
        for (int j = t; j < Hc; j += 256) {
            float v = hr[j]; x[ro + j] = v; x_h[ro + j] = __float2half_rn(v);
        }
        return;
    }
    int wi = w - 1;
    int valid = wvalid[b * Wc + wi];
    const float* hrows[Gc];
    float m[Gc];
    float cnt = 0.f;
#pragma unroll
    for (int g = 0; g < Gc; g++) {
        int idx = wti[(b * Wc + wi) * Gc + g];
        hrows[g] = hidden + (size_t)(b * Sc + idx) * Hc;
        m[g] = gmask[(b * Wc + wi) * Gc + g] ? 1.f : 0.f;
        cnt += m[g];
    }
    float inv = valid ? (1.f / fmaxf(cnt, 1.f)) : 0.f;
    for (int j = t; j < Hc; j += 256) {
        float s = 0.f;
#pragma unroll
        for (int g = 0; g < Gc; g++) s += m[g] * hrows[g][j];
        float v = s * inv;
        x[ro + j] = v; x_h[ro + j] = __float2half_rn(v);
    }
}

// ---------------- shared mma helpers ----------------
__device__ __forceinline__ void ldm4(unsigned* r, unsigned addr) {
    asm volatile("ldmatrix.sync.aligned.m8n8.x4.shared.b16 {%0,%1,%2,%3}, [%4];"
                 : "=r"(r[0]), "=r"(r[1]), "=r"(r[2]), "=r"(r[3]) : "r"(addr));
}
__device__ __forceinline__ void ldm2(unsigned* r, unsigned addr) {
    asm volatile("ldmatrix.sync.aligned.m8n8.x2.shared.b16 {%0,%1}, [%2];"
                 : "=r"(r[0]), "=r"(r[1]) : "r"(addr));
}
__device__ __forceinline__ void mma16(float* d, const unsigned* a, unsigned b0, unsigned b1) {
    asm volatile(
        "mma.sync.aligned.m16n8k16.row.col.f32.f16.f16.f32 "
        "{%0,%1,%2,%3}, {%4,%5,%6,%7}, {%8,%9}, {%0,%1,%2,%3};\n"
        : "+f"(d[0]), "+f"(d[1]), "+f"(d[2]), "+f"(d[3])
        : "r"(a[0]), "r"(a[1]), "r"(a[2]), "r"(a[3]), "r"(b0), "r"(b1));
}
__device__ __forceinline__ void cp16(unsigned dst, const void* src, unsigned sz) {
    asm volatile("cp.async.cg.shared.global [%0], [%1], 16, %2;\n"
                 :: "r"(dst), "l"(src), "r"(sz));
}

// =====================================================================
// FP16 tensor-core GEMM (unchanged from R8 pass)
// =====================================================================
#define BMt 128
#define BNt 128
#define BKt 64
#define STAGES 3
#define SA_BYTES 16384
#define SB_OFF   (STAGES * SA_BYTES)
#define GEMM_SMEM (2 * STAGES * SA_BYTES)

template <int MODE>
__global__ __launch_bounds__(256, 2) void gemm_f16_async(
    const __half* __restrict__ A, const __half* __restrict__ B,
    const float* __restrict__ bias, void* __restrict__ Cout,
    int M, int N, int K)
{
    extern __shared__ char gsm[];
    const unsigned sbase = (unsigned)__cvta_generic_to_shared(gsm);

    const int tid  = threadIdx.x;
    const int warp = tid >> 5;
    const int lane = tid & 31;
    const int wm = warp >> 2;
    const int wn = warp & 3;
    const int rowBase = blockIdx.y * BMt;
    const int colBase = blockIdx.x * BNt;

    const int cc = tid & 7;
    const int cr = tid >> 3;
    const __half* aSrc[4];
    const __half* bSrc[4];
    unsigned aSz[4];
    unsigned dA[4], dB[4];
#pragma unroll
    for (int j = 0; j < 4; j++) {
        int r = cr + 32 * j;
        int grow = rowBase + r;
        aSrc[j] = A + (size_t)grow * K + cc * 8;
        aSz[j]  = (grow < M) ? 16u : 0u;
        bSrc[j] = B + (size_t)(colBase + r) * K + cc * 8;
        unsigned d = r * 128 + ((cc ^ (r & 7)) << 4);
        dA[j] = sbase + d;
        dB[j] = sbase + SB_OFF + d;
    }

    const int wr     = lane & 7;
    const int rowOff = ((lane >> 3) & 1) * 8 + wr;
    const int cAdd   = lane >> 4;
    const unsigned aFragBase = (wm * 64 + rowOff) * 128;
    const unsigned bFragBase = SB_OFF + (wn * 32 + rowOff) * 128;
    unsigned swz[4];
#pragma unroll
    for (int ks = 0; ks < 4; ks++)
        swz[ks] = ((unsigned)((2 * ks + cAdd) ^ wr)) << 4;

    float acc[4][4][4];
#pragma unroll
    for (int i = 0; i < 4; i++)
#pragma unroll
        for (int j = 0; j < 4; j++)
#pragma unroll
            for (int q = 0; q < 4; q++) acc[i][j][q] = 0.f;

    const int nk = K / BKt;

#pragma unroll
    for (int s = 0; s < 2; s++) {
        const int k0 = s * BKt;
        const unsigned so = s * SA_BYTES;
#pragma unroll
        for (int j = 0; j < 4; j++) cp16(dA[j] + so, aSrc[j] + k0, aSz[j]);
#pragma unroll
        for (int j = 0; j < 4; j++) cp16(dB[j] + so, bSrc[j] + k0, 16u);
        asm volatile("cp.async.commit_group;\n");
    }

    for (int t = 0; t < nk; t++) {
        asm volatile("cp.async.wait_group 1;\n");
        __syncthreads();
        if (t + 2 < nk) {
            const int s = (t + 2) % STAGES;
            const int k0 = (t + 2) * BKt;
            const unsigned so = s * SA_BYTES;
#pragma unroll
            for (int j = 0; j < 4; j++) cp16(dA[j] + so, aSrc[j] + k0, aSz[j]);
#pragma unroll
            for (int j = 0; j < 4; j++) cp16(dB[j] + so, bSrc[j] + k0, 16u);
        }
        asm volatile("cp.async.commit_group;\n");

        const unsigned stOff = (t % STAGES) * SA_BYTES;
#pragma unroll
        for (int ks = 0; ks < 4; ks++) {
            const unsigned so = swz[ks] + stOff;
            unsigned af[4][4];
#pragma unroll
            for (int mt = 0; mt < 4; mt++)
                ldm4(af[mt], sbase + aFragBase + mt * 2048 + so);
            unsigned bf[2][4];
#pragma unroll
            for (int ntp = 0; ntp < 2; ntp++)
                ldm4(bf[ntp], sbase + bFragBase + ntp * 2048 + so);
#pragma unroll
            for (int mt = 0; mt < 4; mt++)
#pragma unroll
                for (int ntp = 0; ntp < 2; ntp++)
#pragma unroll
                    for (int ntl = 0; ntl < 2; ntl++)
                        mma16(acc[mt][ntp * 2 + ntl], af[mt],
                              bf[ntp][ntl], bf[ntp][2 + ntl]);
        }
    }

    const int fr = lane >> 2;
    const int fc = lane & 3;
#pragma unroll
    for (int mt = 0; mt < 4; mt++) {
        int row0 = rowBase + wm * 64 + mt * 16 + fr;
#pragma unroll
        for (int nt = 0; nt < 4; nt++) {
            int col = colBase + wn * 32 + nt * 8 + 2 * fc;
            float b0 = bias[col], b1 = bias[col + 1];
            float v0 = acc[mt][nt][0] + b0;
            float v1 = acc[mt][nt][1] + b1;
            float v2 = acc[mt][nt][2] + b0;
            float v3 = acc[mt][nt][3] + b1;
            if (MODE == 1) {
                v0 = fmaxf(v0, 0.f); v1 = fmaxf(v1, 0.f);
                v2 = fmaxf(v2, 0.f); v3 = fmaxf(v3, 0.f);
                __half2* C = (__half2*)Cout;
                if (row0 < M)
                    C[((size_t)row0 * N + col) >> 1] = __floats2half2_rn(v0, v1);
                if (row0 + 8 < M)
                    C[((size_t)(row0 + 8) * N + col) >> 1] = __floats2half2_rn(v2, v3);
            } else {
                float* C = (float*)Cout;
                if (row0 < M)
                    *(float2*)(C + (size_t)row0 * N + col) = make_float2(v0, v1);
                if (row0 + 8 < M)
                    *(float2*)(C + (size_t)(row0 + 8) * N + col) = make_float2(v2, v3);
            }
        }
    }
}

// =====================================================================
// Tensor-core attention: one block per (h, b).
// smem fp16 operands, row stride 384B, chunk swizzle c' = c ^ (row&7).
// S = Q K^T (fp32 acc in smem), softmax, P fp16, O = P V^T -> ctx fp16.
// Q processed in 3 chunks of 48 rows.
// =====================================================================
#define ATT_K_OFF    0
#define ATT_VT_OFF   52224                    // 136 * 384
#define ATT_Q_OFF    (ATT_VT_OFF + 73728)     // 192 * 384
#define ATT_P_OFF    (ATT_Q_OFF + 18432)      // 48 * 384
#define ATT_S_OFF    (ATT_P_OFF + 18432)
#define ATT_SSTRIDE  148                      // floats
#define ATT_BIAS_OFF (ATT_S_OFF + 48 * ATT_SSTRIDE * 4)
#define ATT_SMEM     (ATT_BIAS_OFF + 576)     // 191808 bytes

__global__ __launch_bounds__(256) void attn_mma_kernel(
    const float* __restrict__ qkv, const int* __restrict__ wvalid,
    __half* __restrict__ ctx_h)
{
    extern __shared__ char smemraw[];
    const unsigned sb = (unsigned)__cvta_generic_to_shared(smemraw);
    float* sS    = (float*)(smemraw + ATT_S_OFF);
    float* sBias = (float*)(smemraw + ATT_BIAS_OFF);

    const int h = blockIdx.x, b = blockIdx.y;
    const int tid = threadIdx.x;
    const int warp = tid >> 5, lane = tid & 31;

    const float* kb  = qkv + (size_t)b * Lwc * ROW3H + Hc + h * HDc;
    const float* vbp = kb + Hc;
    const float* qb  = qkv + (size_t)b * Lwc * ROW3H + h * HDc;

    // zero VT pad chunks 16,17 (tokens 128..143; token 128 re-written below)
    for (int i = tid; i < 192 * 2; i += 256) {
        int d = i >> 1, j = i & 1;
        *(uint4*)(smemraw + ATT_VT_OFF + d * 384 + (((16 + j) ^ (d & 7)) << 4)) =
            make_uint4(0, 0, 0, 0);
    }
    __syncthreads();
    // K rows + VT transpose fill
    for (int i = tid; i < 129 * 96; i += 256) {
        int r = i / 96, dp = (i - r * 96) * 2;
        float2 kv = *(const float2*)(kb  + (size_t)r * ROW3H + dp);
        float2 vv = *(const float2*)(vbp + (size_t)r * ROW3H + dp);
        int c = dp >> 3, off = dp & 7;
        *(__half2*)(smemraw + ATT_K_OFF + r * 384 + ((c ^ (r & 7)) << 4) + off * 2) =
            __floats2half2_rn(kv.x, kv.y);
        int cr = r >> 3, offr = r & 7;
        *(__half*)(smemraw + ATT_VT_OFF + dp * 384 + ((cr ^ (dp & 7)) << 4) + offr * 2) =
            __float2half_rn(vv.x);
        *(__half*)(smemraw + ATT_VT_OFF + (dp + 1) * 384 + ((cr ^ ((dp + 1) & 7)) << 4) + offr * 2) =
            __float2half_rn(vv.y);
    }
    for (int i = tid; i < 144; i += 256)
        sBias[i] = (i == 0) ? 0.f : ((i < Lwc && wvalid[b * Wc + i - 1]) ? 0.f : -1e30f);
    __syncthreads();

    // per-lane fragment constants
    const int wr    = lane & 7;
    const int sel8  = (lane >> 3) & 1;
    const int sel16 = lane >> 4;
    const int fr    = lane >> 2;
    const int fc    = lane & 3;
    const unsigned aRow = (unsigned)((sel8 * 8 + wr) * 384);

    for (int ch = 0; ch < 3; ch++) {
        const int q0 = ch * 48;
        const int nq = min(48, Lwc - q0);
        // load Q chunk
        for (int i = tid; i < nq * 96; i += 256) {
            int r = i / 96, dp = (i - r * 96) * 2;
            float2 qv = *(const float2*)(qb + (size_t)(q0 + r) * ROW3H + dp);
            int c = dp >> 3, off = dp & 7;
            *(__half2*)(smemraw + ATT_Q_OFF + r * 384 + ((c ^ (r & 7)) << 4) + off * 2) =
                __floats2half2_rn(qv.x, qv.y);
        }
        __syncthreads();

        // S = Q K^T : tiles m16(x3) x n8(x17), k 12 steps
        for (int idx = warp; idx < 51; idx += 8) {
            int mt = idx / 17, nt = idx - mt * 17;
            float acc[4] = {0.f, 0.f, 0.f, 0.f};
            unsigned aBase = sb + ATT_Q_OFF + mt * 6144 + aRow;
            unsigned bBase = sb + ATT_K_OFF + (nt * 8 + wr) * 384;
#pragma unroll
            for (int ks = 0; ks < 12; ks++) {
                unsigned a[4], bf[2];
                ldm4(a,  aBase + (((2 * ks + sel16) ^ wr) << 4));
                ldm2(bf, bBase + (((2 * ks + sel8) ^ wr) << 4));
                mma16(acc, a, bf[0], bf[1]);
            }
            int r0 = mt * 16 + fr, c0 = nt * 8 + 2 * fc;
            sS[r0 * ATT_SSTRIDE + c0]           = acc[0];
            sS[r0 * ATT_SSTRIDE + c0 + 1]       = acc[1];
            sS[(r0 + 8) * ATT_SSTRIDE + c0]     = acc[2];
            sS[(r0 + 8) * ATT_SSTRIDE + c0 + 1] = acc[3];
        }
        __syncthreads();

        // softmax rows -> P fp16 (cols padded to 144 with zeros)
        for (int r = warp; r < 48; r += 8) {
            float mx = -1e30f;
            for (int k = lane; k < Lwc; k += 32) {
                float v = sS[r * ATT_SSTRIDE + k] * SCALEc + sBias[k];
                sS[r * ATT_SSTRIDE + k] = v;
                mx = fmaxf(mx, v);
            }
#pragma unroll
            for (int o = 16; o > 0; o >>= 1) mx = fmaxf(mx, __shfl_xor_sync(0xffffffffu, mx, o));
            float sum = 0.f;
            for (int k = lane; k < Lwc; k += 32) {
                float e = __expf(sS[r * ATT_SSTRIDE + k] - mx);
                sS[r * ATT_SSTRIDE + k] = e;
                sum += e;
            }
#pragma unroll
            for (int o = 16; o > 0; o >>= 1) sum += __shfl_xor_sync(0xffffffffu, sum, o);
            float inv = 1.f / sum;
            for (int k = lane; k < 144; k += 32) {
                float p = (k < Lwc) ? sS[r * ATT_SSTRIDE + k] * inv : 0.f;
                int c = k >> 3, off = k & 7;
                *(__half*)(smemraw + ATT_P_OFF + r * 384 + ((c ^ (r & 7)) << 4) + off * 2) =
                    __float2half_rn(p);
            }
        }
        __syncthreads();

        // O = P V^T : tiles m16(x3) x n8(x24), k 9 steps
        for (int idx = warp; idx < 72; idx += 8) {
            int mt = idx / 24, nt = idx - mt * 24;
            float acc[4] = {0.f, 0.f, 0.f, 0.f};
            unsigned aBase = sb + ATT_P_OFF + mt * 6144 + aRow;
            unsigned bBase = sb + ATT_VT_OFF + (nt * 8 + wr) * 384;
#pragma unroll
            for (int ks = 0; ks < 9; ks++) {
                unsigned a[4], bf[2];
                ldm4(a,  aBase + (((2 * ks + sel16) ^ wr) << 4));
                ldm2(bf, bBase + (((2 * ks + sel8) ^ wr) << 4));
                mma16(acc, a, bf[0], bf[1]);
            }
            int rloc = mt * 16 + fr;
            int d = nt * 8 + 2 * fc;
            if (rloc < nq)
                *(__half2*)(ctx_h + (size_t)(b * Lwc + q0 + rloc) * Hc + h * HDc + d) =
                    __floats2half2_rn(acc[0], acc[1]);
            if (rloc + 8 < nq)
                *(__half2*)(ctx_h + (size_t)(b * Lwc + q0 + rloc + 8) * Hc + h * HDc + d) =
                    __floats2half2_rn(acc[2], acc[3]);
        }
        __syncthreads();
    }
}

// ---------------- residual add + layernorm ----------------
__global__ __launch_bounds__(256) void add_ln_kernel(
    const float* __restrict__ base, const float* __restrict__ delta,
    const float* __restrict__ sc, const float* __restrict__ bi,
    float* __restrict__ out, __half* __restrict__ out_h)
{
    int row = blockIdx.x, t = threadIdx.x;
    const float* xb = base + (size_t)row * Hc;
    const float* db = delta + (size_t)row * Hc;
    float v[3];
    float s = 0.f, ss = 0.f;
#pragma unroll
    for (int i = 0; i < 3; i++) {
        float a = xb[t + i * 256] + db[t + i * 256];
        v[i] = a; s += a; ss += a * a;
    }
    __shared__ float rs[32], rss[32];
#pragma unroll
    for (int o = 16; o > 0; o >>= 1) {
        s  += __shfl_down_sync(0xffffffffu, s, o);
        ss += __shfl_down_sync(0xffffffffu, ss, o);
    }
    int wid = t >> 5, lane = t & 31;
    if (lane == 0) { rs[wid] = s; rss[wid] = ss; }
    __syncthreads();
    if (wid == 0) {
        s  = (lane < 8) ? rs[lane]  : 0.f;
        ss = (lane < 8) ? rss[lane] : 0.f;
#pragma unroll
        for (int o = 4; o > 0; o >>= 1) {
            s  += __shfl_down_sync(0xffffffffu, s, o);
            ss += __shfl_down_sync(0xffffffffu, ss, o);
        }
        if (lane == 0) { rs[0] = s; rss[0] = ss; }
    }
    __syncthreads();
    float mean = rs[0] * (1.f / Hc);
    float var  = rss[0] * (1.f / Hc) - mean * mean;
    float r = rsqrtf(var + EPSc);
#pragma unroll
    for (int i = 0; i < 3; i++) {
        int j = t + i * 256;
        float o = (v[i] - mean) * r * sc[j] + bi[j];
        out[(size_t)row * Hc + j] = o;
        out_h[(size_t)row * Hc + j] = __float2half_rn(o);
    }
}

// ---------------- classifier + pooled output ----------------
__global__ __launch_bounds__(256) void cls_kernel(
    const float* __restrict__ x, const float* __restrict__ cw,
    const float* __restrict__ cb, float* __restrict__ out)
{
    int b = blockIdx.x, t = threadIdx.x;
    const float* p = x + (size_t)(b * Lwc) * Hc;
    for (int j = t; j < Hc; j += 256) out[Bc * NLABc + b * Hc + j] = p[j];
    int wid = t >> 5, lane = t & 31;
    if (wid < NLABc) {
        float s = 0.f;
        for (int j = lane; j < Hc; j += 32) s += p[j] * cw[wid * Hc + j];
#pragma unroll
        for (int o = 16; o > 0; o >>= 1) s += __shfl_down_sync(0xffffffffu, s, o);
        if (lane == 0) out[b * NLABc + wid] = s + cb[wid];
    }
}

// ---------------- host ----------------
template <typename T>
static T* symaddr(const void* sym) {
    void* p = nullptr;
    cudaGetSymbolAddress(&p, sym);
    return (T*)p;
}

extern "C" void kernel_launch(void* const* d_in, const int* in_sizes, int n_in,
                              void* d_out, int out_size)
{
    const float* hidden = (const float*)d_in[0];
    const int*   wti    = (const int*)  d_in[1];
    const int*   gmask  = (const int*)  d_in[2];
    const int*   wvalid = (const int*)  d_in[3];
    const float* qkv_w  = (const float*)d_in[4];
    const float* qkv_b  = (const float*)d_in[5];
    const float* out_w  = (const float*)d_in[6];
    const float* out_b  = (const float*)d_in[7];
    const float* ff1_w  = (const float*)d_in[8];
    const float* ff1_b  = (const float*)d_in[9];
    const float* ff2_w  = (const float*)d_in[10];
    const float* ff2_b  = (const float*)d_in[11];
    const float* ln1_s  = (const float*)d_in[12];
    const float* ln1_b  = (const float*)d_in[13];
    const float* ln2_s  = (const float*)d_in[14];
    const float* ln2_b  = (const float*)d_in[15];
    const float* cls_w  = (const float*)d_in[16];
    const float* cls_b  = (const float*)d_in[17];
    float* out = (float*)d_out;

    float*  x     = symaddr<float>(g_x);
    __half* x_h   = symaddr<__half>(g_x_h);
    float*  qkv   = symaddr<float>(g_qkv);
    __half* ctx_h = symaddr<__half>(g_ctx_h);
    float*  y     = symaddr<float>(g_y);
    __half* ff_h  = symaddr<__half>(g_ff_h);
    __half* qkvw_h = symaddr<__half>(g_qkvw_h);
    __half* outw_h = symaddr<__half>(g_outw_h);
    __half* ff1w_h = symaddr<__half>(g_ff1w_h);
    __half* ff2w_h = symaddr<__half>(g_ff2w_h);

    static bool attr_done = false;
    if (!attr_done) {
        cudaFuncSetAttribute(gemm_f16_async<0>, cudaFuncAttributeMaxDynamicSharedMemorySize,
                             GEMM_SMEM);
        cudaFuncSetAttribute(gemm_f16_async<1>, cudaFuncAttributeMaxDynamicSharedMemorySize,
                             GEMM_SMEM);
        cudaFuncSetAttribute(attn_mma_kernel, cudaFuncAttributeMaxDynamicSharedMemorySize,
                             ATT_SMEM);
        attr_done = true;
    }

    cvt_all_kernel<<<256, 256>>>(
        (const float4*)qkv_w, (const float4*)out_w,
        (const float4*)ff1_w, (const float4*)ff2_w,
        (uint4*)qkvw_h, (uint4*)outw_h, (uint4*)ff1w_h, (uint4*)ff2w_h);

    build_x_kernel<<<dim3(Lwc, Bc), 256>>>(hidden, wti, gmask, wvalid, x, x_h);

    const int MB = (Mc + BMt - 1) / BMt;     // 33
    dim3 gQKV(3 * Hc / BNt, MB);
    dim3 gH  (Hc / BNt,     MB);
    dim3 gFF (FFc / BNt,    MB);

    for (int l = 0; l < NLc; l++) {
        gemm_f16_async<0><<<gQKV, 256, GEMM_SMEM>>>(
            x_h, qkvw_h + (size_t)l * 3 * Hc * Hc,
            qkv_b + (size_t)l * 3 * Hc, qkv, Mc, 3 * Hc, Hc);
        attn_mma_kernel<<<dim3(NHc, Bc), 256, ATT_SMEM>>>(qkv, wvalid, ctx_h);
        gemm_f16_async<0><<<gH, 256, GEMM_SMEM>>>(
            ctx_h, outw_h + (size_t)l * Hc * Hc,
            out_b + (size_t)l * Hc, y, Mc, Hc, Hc);
        add_ln_kernel<<<Mc, 256>>>(x, y, ln1_s + (size_t)l * Hc, ln1_b + (size_t)l * Hc, x, x_h);
        gemm_f16_async<1><<<gFF, 256, GEMM_SMEM>>>(
            x_h, ff1w_h + (size_t)l * FFc * Hc,
            ff1_b + (size_t)l * FFc, ff_h, Mc, FFc, Hc);
        gemm_f16_async<0><<<gH, 256, GEMM_SMEM>>>(
            ff_h, ff2w_h + (size_t)l * Hc * FFc,
            ff2_b + (size_t)l * Hc, y, Mc, Hc, FFc);
        add_ln_kernel<<<Mc, 256>>>(x, y, ln2_s + (size_t)l * Hc, ln2_b + (size_t)l * Hc, x, x_h);
    }

    cls_kernel<<<Bc, 256>>>(x, cls_w, cls_b, out);
}

// round 15
// speedup vs baseline: 15.9606x; 1.0590x over previous
#include <cuda_runtime.h>
#include <cuda_fp16.h>
#include <math.h>

// ---------------- problem constants ----------------
#define Bc    32
#define Sc    512
#define Hc    768
#define Wc    128
#define Gc    4
#define NHc   4
#define HDc   192
#define FFc   2048
#define NLc   2
#define NLABc 6
#define Lwc   (Wc + 1)          // 129
#define Mc    (Bc * Lwc)        // 4128
#define EPSc  1e-5f
#define SCALEc 0.07216878364870322f  // 1/sqrt(192)
#define LOG2Ec 1.4426950408889634f
#define ROW3H (3 * Hc)

// ---------------- scratch (device globals; no allocs) ----------------
__device__ float  g_x   [Mc * Hc];
__device__ __half g_x_h [Mc * Hc];
__device__ __half g_qkv_h[Mc * ROW3H];     // qkv fp16 (GEMM writes, attention reads)
__device__ __half g_ctx_h[Mc * Hc];
__device__ float  g_y   [Mc * Hc];
__device__ __half g_ff_h[Mc * FFc];
__device__ __half g_qkvw_h[NLc * 3 * Hc * Hc];
__device__ __half g_outw_h[NLc * Hc * Hc];
__device__ __half g_ff1w_h[NLc * FFc * Hc];
__device__ __half g_ff2w_h[NLc * Hc * FFc];

// ---------------- merged weight conversion ----------------
#define CVN1 442368
#define CVN2 147456
#define CVN3 393216
#define CVN4 393216
#define CVT_TOT (CVN1 + CVN2 + CVN3 + CVN4)

__global__ __launch_bounds__(256) void cvt_all_kernel(
    const float4* __restrict__ w1, const float4* __restrict__ w2,
    const float4* __restrict__ w3, const float4* __restrict__ w4,
    uint4* __restrict__ o1, uint4* __restrict__ o2,
    uint4* __restrict__ o3, uint4* __restrict__ o4)
{
    int i = blockIdx.x * blockDim.x + threadIdx.x;
    int stride = gridDim.x * blockDim.x;
    for (; i < CVT_TOT; i += stride) {
        const float4* src; uint4* dst; int j;
        if (i < CVN1)                 { src = w1; dst = o1; j = i; }
        else if (i < CVN1 + CVN2)     { src = w2; dst = o2; j = i - CVN1; }
        else if (i < CVN1 + CVN2 + CVN3) { src = w3; dst = o3; j = i - CVN1 - CVN2; }
        else                          { src = w4; dst = o4; j = i - CVN1 - CVN2 - CVN3; }
        float4 a = src[2 * j], b = src[2 * j + 1];
        __half2 h0 = __floats2half2_rn(a.x, a.y);
        __half2 h1 = __floats2half2_rn(a.z, a.w);
        __half2 h2 = __floats2half2_rn(b.x, b.y);
        __half2 h3 = __floats2half2_rn(b.z, b.w);
        uint4 o;
        o.x = *(unsigned*)&h0; o.y = *(unsigned*)&h1;
        o.z = *(unsigned*)&h2; o.w = *(unsigned*)&h3;
        dst[j] = o;
    }
}

// ---------------- build x ----------------
__global__ __launch_bounds__(256) void build_x_kernel(
    const float* __restrict__ hidden, const int* __restrict__ wti,
    const int* __restrict__ gmask, const int* __restrict__ wvalid,
    float* __restrict__ x, __half* __restrict__ x_h)
{
    int w = blockIdx.x, b = blockIdx.y, t = threadIdx.x;
    size_t ro = (size_t)(b * Lwc + w) * Hc;
    if (w == 0) {
        const float* hr = hidden + (size_t)(b * Sc) * Hc;
        for (int j = t; j < Hc; j += 256) {
            float v = hr[j]; x[ro + j] = v; x_h[ro + j] = __float2half_rn(v);
        }
        return;
    }
    int wi = w - 1;
    int valid = wvalid[b * Wc + wi];
    const float* hrows[Gc];
    float m[Gc];
    float cnt = 0.f;
#pragma unroll
    for (int g = 0; g < Gc; g++) {
        int idx = wti[(b * Wc + wi) * Gc + g];
        hrows[g] = hidden + (size_t)(b * Sc + idx) * Hc;
        m[g] = gmask[(b * Wc + wi) * Gc + g] ? 1.f : 0.f;
        cnt += m[g];
    }
    float inv = valid ? (1.f / fmaxf(cnt, 1.f)) : 0.f;
    for (int j = t; j < Hc; j += 256) {
        float s = 0.f;
#pragma unroll
        for (int g = 0; g < Gc; g++) s += m[g] * hrows[g][j];
        float v = s * inv;
        x[ro + j] = v; x_h[ro + j] = __float2half_rn(v);
    }
}

// ---------------- shared mma helpers ----------------
__device__ __forceinline__ void ldm4(unsigned* r, unsigned addr) {
    asm volatile("ldmatrix.sync.aligned.m8n8.x4.shared.b16 {%0,%1,%2,%3}, [%4];"
                 : "=r"(r[0]), "=r"(r[1]), "=r"(r[2]), "=r"(r[3]) : "r"(addr));
}
__device__ __forceinline__ void ldm2(unsigned* r, unsigned addr) {
    asm volatile("ldmatrix.sync.aligned.m8n8.x2.shared.b16 {%0,%1}, [%2];"
                 : "=r"(r[0]), "=r"(r[1]) : "r"(addr));
}
__device__ __forceinline__ void ldm2t(unsigned* r, unsigned addr) {
    asm volatile("ldmatrix.sync.aligned.m8n8.x2.trans.shared.b16 {%0,%1}, [%2];"
                 : "=r"(r[0]), "=r"(r[1]) : "r"(addr));
}
__device__ __forceinline__ void mma16(float* d, const unsigned* a, unsigned b0, unsigned b1) {
    asm volatile(
        "mma.sync.aligned.m16n8k16.row.col.f32.f16.f16.f32 "
        "{%0,%1,%2,%3}, {%4,%5,%6,%7}, {%8,%9}, {%0,%1,%2,%3};\n"
        : "+f"(d[0]), "+f"(d[1]), "+f"(d[2]), "+f"(d[3])
        : "r"(a[0]), "r"(a[1]), "r"(a[2]), "r"(a[3]), "r"(b0), "r"(b1));
}
__device__ __forceinline__ void cp16(unsigned dst, const void* src, unsigned sz) {
    asm volatile("cp.async.cg.shared.global [%0], [%1], 16, %2;\n"
                 :: "r"(dst), "l"(src), "r"(sz));
}

// =====================================================================
// FP16 tensor-core GEMM.  MODE 0: fp32 out. 1: relu+fp16. 2: fp16.
// =====================================================================
#define BMt 128
#define BNt 128
#define BKt 64
#define STAGES 3
#define SA_BYTES 16384
#define SB_OFF   (STAGES * SA_BYTES)
#define GEMM_SMEM (2 * STAGES * SA_BYTES)

template <int MODE>
__global__ __launch_bounds__(256, 2) void gemm_f16_async(
    const __half* __restrict__ A, const __half* __restrict__ B,
    const float* __restrict__ bias, void* __restrict__ Cout,
    int M, int N, int K)
{
    extern __shared__ char gsm[];
    const unsigned sbase = (unsigned)__cvta_generic_to_shared(gsm);

    const int tid  = threadIdx.x;
    const int warp = tid >> 5;
    const int lane = tid & 31;
    const int wm = warp >> 2;
    const int wn = warp & 3;
    const int rowBase = blockIdx.y * BMt;
    const int colBase = blockIdx.x * BNt;

    const int cc = tid & 7;
    const int cr = tid >> 3;
    const __half* aSrc[4];
    const __half* bSrc[4];
    unsigned aSz[4];
    unsigned dA[4], dB[4];
#pragma unroll
    for (int j = 0; j < 4; j++) {
        int r = cr + 32 * j;
        int grow = rowBase + r;
        aSrc[j] = A + (size_t)grow * K + cc * 8;
        aSz[j]  = (grow < M) ? 16u : 0u;
        bSrc[j] = B + (size_t)(colBase + r) * K + cc * 8;
        unsigned d = r * 128 + ((cc ^ (r & 7)) << 4);
        dA[j] = sbase + d;
        dB[j] = sbase + SB_OFF + d;
    }

    const int wr     = lane & 7;
    const int rowOff = ((lane >> 3) & 1) * 8 + wr;
    const int cAdd   = lane >> 4;
    const unsigned aFragBase = (wm * 64 + rowOff) * 128;
    const unsigned bFragBase = SB_OFF + (wn * 32 + rowOff) * 128;
    unsigned swz[4];
#pragma unroll
    for (int ks = 0; ks < 4; ks++)
        swz[ks] = ((unsigned)((2 * ks + cAdd) ^ wr)) << 4;

    float acc[4][4][4];
#pragma unroll
    for (int i = 0; i < 4; i++)
#pragma unroll
        for (int j = 0; j < 4; j++)
#pragma unroll
            for (int q = 0; q < 4; q++) acc[i][j][q] = 0.f;

    const int nk = K / BKt;

#pragma unroll
    for (int s = 0; s < 2; s++) {
        const int k0 = s * BKt;
        const unsigned so = s * SA_BYTES;
#pragma unroll
        for (int j = 0; j < 4; j++) cp16(dA[j] + so, aSrc[j] + k0, aSz[j]);
#pragma unroll
        for (int j = 0; j < 4; j++) cp16(dB[j] + so, bSrc[j] + k0, 16u);
        asm volatile("cp.async.commit_group;\n");
    }

    for (int t = 0; t < nk; t++) {
        asm volatile("cp.async.wait_group 1;\n");
        __syncthreads();
        if (t + 2 < nk) {
            const int s = (t + 2) % STAGES;
            const int k0 = (t + 2) * BKt;
            const unsigned so = s * SA_BYTES;
#pragma unroll
            for (int j = 0; j < 4; j++) cp16(dA[j] + so, aSrc[j] + k0, aSz[j]);
#pragma unroll
            for (int j = 0; j < 4; j++) cp16(dB[j] + so, bSrc[j] + k0, 16u);
        }
        asm volatile("cp.async.commit_group;\n");

        const unsigned stOff = (t % STAGES) * SA_BYTES;
#pragma unroll
        for (int ks = 0; ks < 4; ks++) {
            const unsigned so = swz[ks] + stOff;
            unsigned af[4][4];
#pragma unroll
            for (int mt = 0; mt < 4; mt++)
                ldm4(af[mt], sbase + aFragBase + mt * 2048 + so);
            unsigned bf[2][4];
#pragma unroll
            for (int ntp = 0; ntp < 2; ntp++)
                ldm4(bf[ntp], sbase + bFragBase + ntp * 2048 + so);
#pragma unroll
            for (int mt = 0; mt < 4; mt++)
#pragma unroll
                for (int ntp = 0; ntp < 2; ntp++)
#pragma unroll
                    for (int ntl = 0; ntl < 2; ntl++)
                        mma16(acc[mt][ntp * 2 + ntl], af[mt],
                              bf[ntp][ntl], bf[ntp][2 + ntl]);
        }
    }

    const int fr = lane >> 2;
    const int fc = lane & 3;
#pragma unroll
    for (int mt = 0; mt < 4; mt++) {
        int row0 = rowBase + wm * 64 + mt * 16 + fr;
#pragma unroll
        for (int nt = 0; nt < 4; nt++) {
            int col = colBase + wn * 32 + nt * 8 + 2 * fc;
            float b0 = bias[col], b1 = bias[col + 1];
            float v0 = acc[mt][nt][0] + b0;
            float v1 = acc[mt][nt][1] + b1;
            float v2 = acc[mt][nt][2] + b0;
            float v3 = acc[mt][nt][3] + b1;
            if (MODE >= 1) {
                if (MODE == 1) {
                    v0 = fmaxf(v0, 0.f); v1 = fmaxf(v1, 0.f);
                    v2 = fmaxf(v2, 0.f); v3 = fmaxf(v3, 0.f);
                }
                __half2* C = (__half2*)Cout;
                if (row0 < M)
                    C[((size_t)row0 * N + col) >> 1] = __floats2half2_rn(v0, v1);
                if (row0 + 8 < M)
                    C[((size_t)(row0 + 8) * N + col) >> 1] = __floats2half2_rn(v2, v3);
            } else {
                float* C = (float*)Cout;
                if (row0 < M)
                    *(float2*)(C + (size_t)row0 * N + col) = make_float2(v0, v1);
                if (row0 + 8 < M)
                    *(float2*)(C + (size_t)(row0 + 8) * N + col) = make_float2(v2, v3);
            }
        }
    }
}

// =====================================================================
// Tensor-core attention v2: qkv fp16, cp.async fills, V row-major with
// ldmatrix.trans (no transpose fill). One block per (h, b).
// Rows 384B, chunk swizzle c' = c ^ (row&7).
// =====================================================================
#define ATT_K_OFF    0                        // 136 rows * 384
#define ATT_V_OFF    52224                    // 144 rows * 384
#define ATT_Q_OFF    107520                   // 48 * 384
#define ATT_P_OFF    125952                   // 48 * 384
#define ATT_S_OFF    144384                   // 48 * 148 * 4
#define ATT_SSTRIDE  148
#define ATT_BIAS_OFF 172800                   // 144 * 4
#define ATT_SMEM     173376

__global__ __launch_bounds__(256) void attn_mma_kernel(
    const __half* __restrict__ qkv, const int* __restrict__ wvalid,
    __half* __restrict__ ctx_h)
{
    extern __shared__ char smemraw[];
    const unsigned sb = (unsigned)__cvta_generic_to_shared(smemraw);
    float* sS    = (float*)(smemraw + ATT_S_OFF);
    float* sBias = (float*)(smemraw + ATT_BIAS_OFF);

    const int h = blockIdx.x, b = blockIdx.y;
    const int tid = threadIdx.x;
    const int warp = tid >> 5, lane = tid & 31;

    const __half* kb = qkv + (size_t)b * Lwc * ROW3H + Hc + h * HDc;
    const __half* vb = kb + Hc;
    const __half* qb = qkv + (size_t)b * Lwc * ROW3H + h * HDc;

    // zero pad rows: K 129..135 (7 rows), V 129..143 (15 rows)
    for (int i = tid; i < 22 * 24; i += 256) {
        int rr = i / 24, c = i - rr * 24;
        unsigned off = (rr < 7) ? (ATT_K_OFF + (129 + rr) * 384)
                                : (ATT_V_OFF + (129 + rr - 7) * 384);
        *(uint4*)(smemraw + off + c * 16) = make_uint4(0, 0, 0, 0);
    }
    // K + V via cp.async (129 rows x 24 chunks each)
    for (int i = tid; i < 2 * 129 * 24; i += 256) {
        int isV = (i >= 129 * 24);
        int j = isV ? i - 129 * 24 : i;
        int r = j / 24, c = j - r * 24;
        unsigned dst = sb + (isV ? ATT_V_OFF : ATT_K_OFF)
                     + r * 384 + ((c ^ (r & 7)) << 4);
        const __half* src = (isV ? vb : kb) + (size_t)r * ROW3H + c * 8;
        cp16(dst, src, 16u);
    }
    asm volatile("cp.async.commit_group;\n");
    for (int i = tid; i < 144; i += 256)
        sBias[i] = (i == 0) ? 0.f : ((i < Lwc && wvalid[b * Wc + i - 1]) ? 0.f : -1.0e30f);
    asm volatile("cp.async.wait_group 0;\n");
    __syncthreads();

    // per-lane fragment constants
    const int wr    = lane & 7;
    const int sel8  = (lane >> 3) & 1;
    const int sel16 = lane >> 4;
    const int fr    = lane >> 2;
    const int fc    = lane & 3;
    const unsigned aRow = (unsigned)((sel8 * 8 + wr) * 384);
    const float scale2 = SCALEc * LOG2Ec;

    for (int ch = 0; ch < 3; ch++) {
        const int q0 = ch * 48;
        const int nq = min(48, Lwc - q0);
        // Q chunk via cp.async
        for (int i = tid; i < nq * 24; i += 256) {
            int r = i / 24, c = i - r * 24;
            cp16(sb + ATT_Q_OFF + r * 384 + ((c ^ (r & 7)) << 4),
                 qb + (size_t)(q0 + r) * ROW3H + c * 8, 16u);
        }
        asm volatile("cp.async.commit_group;\ncp.async.wait_group 0;\n");
        __syncthreads();

        // S = Q K^T : m16(x3) x n8(x17), 12 k-steps
        for (int idx = warp; idx < 51; idx += 8) {
            int mt = idx / 17, nt = idx - mt * 17;
            float acc[4] = {0.f, 0.f, 0.f, 0.f};
            unsigned aBase = sb + ATT_Q_OFF + mt * 6144 + aRow;
            unsigned bBase = sb + ATT_K_OFF + (nt * 8 + wr) * 384;
#pragma unroll
            for (int ks = 0; ks < 12; ks++) {
                unsigned a[4], bf[2];
                ldm4(a,  aBase + (((2 * ks + sel16) ^ wr) << 4));
                ldm2(bf, bBase + (((2 * ks + sel8) ^ wr) << 4));
                mma16(acc, a, bf[0], bf[1]);
            }
            int r0 = mt * 16 + fr, c0 = nt * 8 + 2 * fc;
            sS[r0 * ATT_SSTRIDE + c0]           = acc[0];
            sS[r0 * ATT_SSTRIDE + c0 + 1]       = acc[1];
            sS[(r0 + 8) * ATT_SSTRIDE + c0]     = acc[2];
            sS[(r0 + 8) * ATT_SSTRIDE + c0 + 1] = acc[3];
        }
        __syncthreads();

        // softmax (base-2) -> P fp16 (cols padded to 144 with zeros)
        for (int r = warp; r < 48; r += 8) {
            float mx = -1e30f;
            for (int k = lane; k < Lwc; k += 32) {
                float v = sS[r * ATT_SSTRIDE + k] * scale2 + sBias[k];
                sS[r * ATT_SSTRIDE + k] = v;
                mx = fmaxf(mx, v);
            }
#pragma unroll
            for (int o = 16; o > 0; o >>= 1) mx = fmaxf(mx, __shfl_xor_sync(0xffffffffu, mx, o));
            float sum = 0.f;
            for (int k = lane; k < Lwc; k += 32) {
                float e = exp2f(sS[r * ATT_SSTRIDE + k] - mx);
                sS[r * ATT_SSTRIDE + k] = e;
                sum += e;
            }
#pragma unroll
            for (int o = 16; o > 0; o >>= 1) sum += __shfl_xor_sync(0xffffffffu, sum, o);
            float inv = 1.f / sum;
            for (int k = lane; k < 144; k += 32) {
                float p = (k < Lwc) ? sS[r * ATT_SSTRIDE + k] * inv : 0.f;
                int c = k >> 3, off = k & 7;
                *(__half*)(smemraw + ATT_P_OFF + r * 384 + ((c ^ (r & 7)) << 4) + off * 2) =
                    __float2half_rn(p);
            }
        }
        __syncthreads();

        // O = P V : m16(x3) x n8(x24), 9 k-steps; V row-major via ldmatrix.trans
        for (int idx = warp; idx < 72; idx += 8) {
            int mt = idx / 24, nt = idx - mt * 24;
            float acc[4] = {0.f, 0.f, 0.f, 0.f};
            unsigned aBase = sb + ATT_P_OFF + mt * 6144 + aRow;
            const unsigned vRow = (sel8 * 8 + wr) * 384;
            const unsigned vChunk = ((unsigned)(nt ^ wr)) << 4;
#pragma unroll
            for (int ks = 0; ks < 9; ks++) {
                unsigned a[4], bf[2];
                ldm4(a, aBase + (((2 * ks + sel16) ^ wr) << 4));
                ldm2t(bf, sb + ATT_V_OFF + ks * 6144 + vRow + vChunk);
                mma16(acc, a, bf[0], bf[1]);
            }
            int rloc = mt * 16 + fr;
            int d = nt * 8 + 2 * fc;
            if (rloc < nq)
                *(__half2*)(ctx_h + (size_t)(b * Lwc + q0 + rloc) * Hc + h * HDc + d) =
                    __floats2half2_rn(acc[0], acc[1]);
            if (rloc + 8 < nq)
                *(__half2*)(ctx_h + (size_t)(b * Lwc + q0 + rloc + 8) * Hc + h * HDc + d) =
                    __floats2half2_rn(acc[2], acc[3]);
        }
        __syncthreads();
    }
}

// ---------------- residual add + layernorm ----------------
__global__ __launch_bounds__(256) void add_ln_kernel(
    const float* __restrict__ base, const float* __restrict__ delta,
    const float* __restrict__ sc, const float* __restrict__ bi,
    float* __restrict__ out, __half* __restrict__ out_h)
{
    int row = blockIdx.x, t = threadIdx.x;
    const float* xb = base + (size_t)row * Hc;
    const float* db = delta + (size_t)row * Hc;
    float v[3];
    float s = 0.f, ss = 0.f;
#pragma unroll
    for (int i = 0; i < 3; i++) {
        float a = xb[t + i * 256] + db[t + i * 256];
        v[i] = a; s += a; ss += a * a;
    }
    __shared__ float rs[32], rss[32];
#pragma unroll
    for (int o = 16; o > 0; o >>= 1) {
        s  += __shfl_down_sync(0xffffffffu, s, o);
        ss += __shfl_down_sync(0xffffffffu, ss, o);
    }
    int wid = t >> 5, lane = t & 31;
    if (lane == 0) { rs[wid] = s; rss[wid] = ss; }
    __syncthreads();
    if (wid == 0) {
        s  = (lane < 8) ? rs[lane]  : 0.f;
        ss = (lane < 8) ? rss[lane] : 0.f;
#pragma unroll
        for (int o = 4; o > 0; o >>= 1) {
            s  += __shfl_down_sync(0xffffffffu, s, o);
            ss += __shfl_down_sync(0xffffffffu, ss, o);
        }
        if (lane == 0) { rs[0] = s; rss[0] = ss; }
    }
    __syncthreads();
    float mean = rs[0] * (1.f / Hc);
    float var  = rss[0] * (1.f / Hc) - mean * mean;
    float r = rsqrtf(var + EPSc);
#pragma unroll
    for (int i = 0; i < 3; i++) {
        int j = t + i * 256;
        float o = (v[i] - mean) * r * sc[j] + bi[j];
        out[(size_t)row * Hc + j] = o;
        out_h[(size_t)row * Hc + j] = __float2half_rn(o);
    }
}

// ---------------- classifier + pooled output ----------------
__global__ __launch_bounds__(256) void cls_kernel(
    const float* __restrict__ x, const float* __restrict__ cw,
    const float* __restrict__ cb, float* __restrict__ out)
{
    int b = blockIdx.x, t = threadIdx.x;
    const float* p = x + (size_t)(b * Lwc) * Hc;
    for (int j = t; j < Hc; j += 256) out[Bc * NLABc + b * Hc + j] = p[j];
    int wid = t >> 5, lane = t & 31;
    if (wid < NLABc) {
        float s = 0.f;
        for (int j = lane; j < Hc; j += 32) s += p[j] * cw[wid * Hc + j];
#pragma unroll
        for (int o = 16; o > 0; o >>= 1) s += __shfl_down_sync(0xffffffffu, s, o);
        if (lane == 0) out[b * NLABc + wid] = s + cb[wid];
    }
}

// ---------------- host ----------------
template <typename T>
static T* symaddr(const void* sym) {
    void* p = nullptr;
    cudaGetSymbolAddress(&p, sym);
    return (T*)p;
}

extern "C" void kernel_launch(void* const* d_in, const int* in_sizes, int n_in,
                              void* d_out, int out_size)
{
    const float* hidden = (const float*)d_in[0];
    const int*   wti    = (const int*)  d_in[1];
    const int*   gmask  = (const int*)  d_in[2];
    const int*   wvalid = (const int*)  d_in[3];
    const float* qkv_w  = (const float*)d_in[4];
    const float* qkv_b  = (const float*)d_in[5];
    const float* out_w  = (const float*)d_in[6];
    const float* out_b  = (const float*)d_in[7];
    const float* ff1_w  = (const float*)d_in[8];
    const float* ff1_b  = (const float*)d_in[9];
    const float* ff2_w  = (const float*)d_in[10];
    const float* ff2_b  = (const float*)d_in[11];
    const float* ln1_s  = (const float*)d_in[12];
    const float* ln1_b  = (const float*)d_in[13];
    const float* ln2_s  = (const float*)d_in[14];
    const float* ln2_b  = (const float*)d_in[15];
    const float* cls_w  = (const float*)d_in[16];
    const float* cls_b  = (const float*)d_in[17];
    float* out = (float*)d_out;

    float*  x     = symaddr<float>(g_x);
    __half* x_h   = symaddr<__half>(g_x_h);
    __half* qkv_h = symaddr<__half>(g_qkv_h);
    __half* ctx_h = symaddr<__half>(g_ctx_h);
    float*  y     = symaddr<float>(g_y);
    __half* ff_h  = symaddr<__half>(g_ff_h);
    __half* qkvw_h = symaddr<__half>(g_qkvw_h);
    __half* outw_h = symaddr<__half>(g_outw_h);
    __half* ff1w_h = symaddr<__half>(g_ff1w_h);
    __half* ff2w_h = symaddr<__half>(g_ff2w_h);

    static bool attr_done = false;
    if (!attr_done) {
        cudaFuncSetAttribute(gemm_f16_async<0>, cudaFuncAttributeMaxDynamicSharedMemorySize,
                             GEMM_SMEM);
        cudaFuncSetAttribute(gemm_f16_async<1>, cudaFuncAttributeMaxDynamicSharedMemorySize,
                             GEMM_SMEM);
        cudaFuncSetAttribute(gemm_f16_async<2>, cudaFuncAttributeMaxDynamicSharedMemorySize,
                             GEMM_SMEM);
        cudaFuncSetAttribute(attn_mma_kernel, cudaFuncAttributeMaxDynamicSharedMemorySize,
                             ATT_SMEM);
        attr_done = true;
    }

    cvt_all_kernel<<<256, 256>>>(
        (const float4*)qkv_w, (const float4*)out_w,
        (const float4*)ff1_w, (const float4*)ff2_w,
        (uint4*)qkvw_h, (uint4*)outw_h, (uint4*)ff1w_h, (uint4*)ff2w_h);

    build_x_kernel<<<dim3(Lwc, Bc), 256>>>(hidden, wti, gmask, wvalid, x, x_h);

    const int MB = (Mc + BMt - 1) / BMt;     // 33
    dim3 gQKV(3 * Hc / BNt, MB);
    dim3 gH  (Hc / BNt,     MB);
    dim3 gFF (FFc / BNt,    MB);

    for (int l = 0; l < NLc; l++) {
        gemm_f16_async<2><<<gQKV, 256, GEMM_SMEM>>>(
            x_h, qkvw_h + (size_t)l * 3 * Hc * Hc,
            qkv_b + (size_t)l * 3 * Hc, qkv_h, Mc, 3 * Hc, Hc);
        attn_mma_kernel<<<dim3(NHc, Bc), 256, ATT_SMEM>>>(qkv_h, wvalid, ctx_h);
        gemm_f16_async<0><<<gH, 256, GEMM_SMEM>>>(
            ctx_h, outw_h + (size_t)l * Hc * Hc,
            out_b + (size_t)l * Hc, y, Mc, Hc, Hc);
        add_ln_kernel<<<Mc, 256>>>(x, y, ln1_s + (size_t)l * Hc, ln1_b + (size_t)l * Hc, x, x_h);
        gemm_f16_async<1><<<gFF, 256, GEMM_SMEM>>>(
            x_h, ff1w_h + (size_t)l * FFc * Hc,
            ff1_b + (size_t)l * FFc, ff_h, Mc, FFc, Hc);
        gemm_f16_async<0><<<gH, 256, GEMM_SMEM>>>(
            ff_h, ff2w_h + (size_t)l * Hc * FFc,
            ff2_b + (size_t)l * Hc, y, Mc, Hc, FFc);
        add_ln_kernel<<<Mc, 256>>>(x, y, ln2_s + (size_t)l * Hc, ln2_b + (size_t)l * Hc, x, x_h);
    }

    cls_kernel<<<Bc, 256>>>(x, cls_w, cls_b, out);
}

// round 16
// speedup vs baseline: 16.7458x; 1.0492x over previous
#include <cuda_runtime.h>
#include <cuda_fp16.h>
#include <math.h>

// ---------------- problem constants ----------------
#define Bc    32
#define Sc    512
#define Hc    768
#define Wc    128
#define Gc    4
#define NHc   4
#define HDc   192
#define FFc   2048
#define NLc   2
#define NLABc 6
#define Lwc   (Wc + 1)          // 129
#define Mc    (Bc * Lwc)        // 4128
#define EPSc  1e-5f
#define SCALEc 0.07216878364870322f  // 1/sqrt(192)
#define LOG2Ec 1.4426950408889634f
#define ROW3H (3 * Hc)

// ---------------- scratch (device globals; no allocs) ----------------
__device__ float  g_x   [Mc * Hc];
__device__ __half g_x_h [Mc * Hc];
__device__ __half g_qkv_h[Mc * ROW3H];
__device__ __half g_ctx_h[Mc * Hc];
__device__ float  g_y   [Mc * Hc];
__device__ __half g_ff_h[Mc * FFc];
__device__ __half g_qkvw_h[NLc * 3 * Hc * Hc];
__device__ __half g_outw_h[NLc * Hc * Hc];
__device__ __half g_ff1w_h[NLc * FFc * Hc];
__device__ __half g_ff2w_h[NLc * Hc * FFc];

// ---------------- merged weight conversion ----------------
#define CVN1 442368
#define CVN2 147456
#define CVN3 393216
#define CVN4 393216
#define CVT_TOT (CVN1 + CVN2 + CVN3 + CVN4)

__global__ __launch_bounds__(256) void cvt_all_kernel(
    const float4* __restrict__ w1, const float4* __restrict__ w2,
    const float4* __restrict__ w3, const float4* __restrict__ w4,
    uint4* __restrict__ o1, uint4* __restrict__ o2,
    uint4* __restrict__ o3, uint4* __restrict__ o4)
{
    int i = blockIdx.x * blockDim.x + threadIdx.x;
    int stride = gridDim.x * blockDim.x;
    for (; i < CVT_TOT; i += stride) {
        const float4* src; uint4* dst; int j;
        if (i < CVN1)                 { src = w1; dst = o1; j = i; }
        else if (i < CVN1 + CVN2)     { src = w2; dst = o2; j = i - CVN1; }
        else if (i < CVN1 + CVN2 + CVN3) { src = w3; dst = o3; j = i - CVN1 - CVN2; }
        else                          { src = w4; dst = o4; j = i - CVN1 - CVN2 - CVN3; }
        float4 a = src[2 * j], b = src[2 * j + 1];
        __half2 h0 = __floats2half2_rn(a.x, a.y);
        __half2 h1 = __floats2half2_rn(a.z, a.w);
        __half2 h2 = __floats2half2_rn(b.x, b.y);
        __half2 h3 = __floats2half2_rn(b.z, b.w);
        uint4 o;
        o.x = *(unsigned*)&h0; o.y = *(unsigned*)&h1;
        o.z = *(unsigned*)&h2; o.w = *(unsigned*)&h3;
        dst[j] = o;
    }
}

// ---------------- build x ----------------
__global__ __launch_bounds__(256) void build_x_kernel(
    const float* __restrict__ hidden, const int* __restrict__ wti,
    const int* __restrict__ gmask, const int* __restrict__ wvalid,
    float* __restrict__ x, __half* __restrict__ x_h)
{
    int w = blockIdx.x, b = blockIdx.y, t = threadIdx.x;
    size_t ro = (size_t)(b * Lwc + w) * Hc;
    if (w == 0) {
        const float* hr = hidden + (size_t)(b * Sc) * Hc;
        for (int j = t; j < Hc; j += 256) {
            float v = hr[j]; x[ro + j] = v; x_h[ro + j] = __float2half_rn(v);
        }
        return;
    }
    int wi = w - 1;
    int valid = wvalid[b * Wc + wi];
    const float* hrows[Gc];
    float m[Gc];
    float cnt = 0.f;
#pragma unroll
    for (int g = 0; g < Gc; g++) {
        int idx = wti[(b * Wc + wi) * Gc + g];
        hrows[g] = hidden + (size_t)(b * Sc + idx) * Hc;
        m[g] = gmask[(b * Wc + wi) * Gc + g] ? 1.f : 0.f;
        cnt += m[g];
    }
    float inv = valid ? (1.f / fmaxf(cnt, 1.f)) : 0.f;
    for (int j = t; j < Hc; j += 256) {
        float s = 0.f;
#pragma unroll
        for (int g = 0; g < Gc; g++) s += m[g] * hrows[g][j];
        float v = s * inv;
        x[ro + j] = v; x_h[ro + j] = __float2half_rn(v);
    }
}

// ---------------- shared mma helpers ----------------
__device__ __forceinline__ void ldm4(unsigned* r, unsigned addr) {
    asm volatile("ldmatrix.sync.aligned.m8n8.x4.shared.b16 {%0,%1,%2,%3}, [%4];"
                 : "=r"(r[0]), "=r"(r[1]), "=r"(r[2]), "=r"(r[3]) : "r"(addr));
}
__device__ __forceinline__ void ldm2(unsigned* r, unsigned addr) {
    asm volatile("ldmatrix.sync.aligned.m8n8.x2.shared.b16 {%0,%1}, [%2];"
                 : "=r"(r[0]), "=r"(r[1]) : "r"(addr));
}
__device__ __forceinline__ void ldm2t(unsigned* r, unsigned addr) {
    asm volatile("ldmatrix.sync.aligned.m8n8.x2.trans.shared.b16 {%0,%1}, [%2];"
                 : "=r"(r[0]), "=r"(r[1]) : "r"(addr));
}
__device__ __forceinline__ void mma16(float* d, const unsigned* a, unsigned b0, unsigned b1) {
    asm volatile(
        "mma.sync.aligned.m16n8k16.row.col.f32.f16.f16.f32 "
        "{%0,%1,%2,%3}, {%4,%5,%6,%7}, {%8,%9}, {%0,%1,%2,%3};\n"
        : "+f"(d[0]), "+f"(d[1]), "+f"(d[2]), "+f"(d[3])
        : "r"(a[0]), "r"(a[1]), "r"(a[2]), "r"(a[3]), "r"(b0), "r"(b1));
}
__device__ __forceinline__ void cp16(unsigned dst, const void* src, unsigned sz) {
    asm volatile("cp.async.cg.shared.global [%0], [%1], 16, %2;\n"
                 :: "r"(dst), "l"(src), "r"(sz));
}

// =====================================================================
// FP16 tensor-core GEMM.  MODE 0: fp32 out. 1: relu+fp16. 2: fp16.
// =====================================================================
#define BMt 128
#define BNt 128
#define BKt 64
#define STAGES 3
#define SA_BYTES 16384
#define SB_OFF   (STAGES * SA_BYTES)
#define GEMM_SMEM (2 * STAGES * SA_BYTES)

template <int MODE>
__global__ __launch_bounds__(256, 2) void gemm_f16_async(
    const __half* __restrict__ A, const __half* __restrict__ B,
    const float* __restrict__ bias, void* __restrict__ Cout,
    int M, int N, int K)
{
    extern __shared__ char gsm[];
    const unsigned sbase = (unsigned)__cvta_generic_to_shared(gsm);

    const int tid  = threadIdx.x;
    const int warp = tid >> 5;
    const int lane = tid & 31;
    const int wm = warp >> 2;
    const int wn = warp & 3;
    const int rowBase = blockIdx.y * BMt;
    const int colBase = blockIdx.x * BNt;

    const int cc = tid & 7;
    const int cr = tid >> 3;
    const __half* aSrc[4];
    const __half* bSrc[4];
    unsigned aSz[4];
    unsigned dA[4], dB[4];
#pragma unroll
    for (int j = 0; j < 4; j++) {
        int r = cr + 32 * j;
        int grow = rowBase + r;
        aSrc[j] = A + (size_t)grow * K + cc * 8;
        aSz[j]  = (grow < M) ? 16u : 0u;
        bSrc[j] = B + (size_t)(colBase + r) * K + cc * 8;
        unsigned d = r * 128 + ((cc ^ (r & 7)) << 4);
        dA[j] = sbase + d;
        dB[j] = sbase + SB_OFF + d;
    }

    const int wr     = lane & 7;
    const int rowOff = ((lane >> 3) & 1) * 8 + wr;
    const int cAdd   = lane >> 4;
    const unsigned aFragBase = (wm * 64 + rowOff) * 128;
    const unsigned bFragBase = SB_OFF + (wn * 32 + rowOff) * 128;
    unsigned swz[4];
#pragma unroll
    for (int ks = 0; ks < 4; ks++)
        swz[ks] = ((unsigned)((2 * ks + cAdd) ^ wr)) << 4;

    float acc[4][4][4];
#pragma unroll
    for (int i = 0; i < 4; i++)
#pragma unroll
        for (int j = 0; j < 4; j++)
#pragma unroll
            for (int q = 0; q < 4; q++) acc[i][j][q] = 0.f;

    const int nk = K / BKt;

#pragma unroll
    for (int s = 0; s < 2; s++) {
        const int k0 = s * BKt;
        const unsigned so = s * SA_BYTES;
#pragma unroll
        for (int j = 0; j < 4; j++) cp16(dA[j] + so, aSrc[j] + k0, aSz[j]);
#pragma unroll
        for (int j = 0; j < 4; j++) cp16(dB[j] + so, bSrc[j] + k0, 16u);
        asm volatile("cp.async.commit_group;\n");
    }

    for (int t = 0; t < nk; t++) {
        asm volatile("cp.async.wait_group 1;\n");
        __syncthreads();
        if (t + 2 < nk) {
            const int s = (t + 2) % STAGES;
            const int k0 = (t + 2) * BKt;
            const unsigned so = s * SA_BYTES;
#pragma unroll
            for (int j = 0; j < 4; j++) cp16(dA[j] + so, aSrc[j] + k0, aSz[j]);
#pragma unroll
            for (int j = 0; j < 4; j++) cp16(dB[j] + so, bSrc[j] + k0, 16u);
        }
        asm volatile("cp.async.commit_group;\n");

        const unsigned stOff = (t % STAGES) * SA_BYTES;
#pragma unroll
        for (int ks = 0; ks < 4; ks++) {
            const unsigned so = swz[ks] + stOff;
            unsigned af[4][4];
#pragma unroll
            for (int mt = 0; mt < 4; mt++)
                ldm4(af[mt], sbase + aFragBase + mt * 2048 + so);
            unsigned bf[2][4];
#pragma unroll
            for (int ntp = 0; ntp < 2; ntp++)
                ldm4(bf[ntp], sbase + bFragBase + ntp * 2048 + so);
#pragma unroll
            for (int mt = 0; mt < 4; mt++)
#pragma unroll
                for (int ntp = 0; ntp < 2; ntp++)
#pragma unroll
                    for (int ntl = 0; ntl < 2; ntl++)
                        mma16(acc[mt][ntp * 2 + ntl], af[mt],
                              bf[ntp][ntl], bf[ntp][2 + ntl]);
        }
    }

    const int fr = lane >> 2;
    const int fc = lane & 3;
#pragma unroll
    for (int mt = 0; mt < 4; mt++) {
        int row0 = rowBase + wm * 64 + mt * 16 + fr;
#pragma unroll
        for (int nt = 0; nt < 4; nt++) {
            int col = colBase + wn * 32 + nt * 8 + 2 * fc;
            float b0 = bias[col], b1 = bias[col + 1];
            float v0 = acc[mt][nt][0] + b0;
            float v1 = acc[mt][nt][1] + b1;
            float v2 = acc[mt][nt][2] + b0;
            float v3 = acc[mt][nt][3] + b1;
            if (MODE >= 1) {
                if (MODE == 1) {
                    v0 = fmaxf(v0, 0.f); v1 = fmaxf(v1, 0.f);
                    v2 = fmaxf(v2, 0.f); v3 = fmaxf(v3, 0.f);
                }
                __half2* C = (__half2*)Cout;
                if (row0 < M)
                    C[((size_t)row0 * N + col) >> 1] = __floats2half2_rn(v0, v1);
                if (row0 + 8 < M)
                    C[((size_t)(row0 + 8) * N + col) >> 1] = __floats2half2_rn(v2, v3);
            } else {
                float* C = (float*)Cout;
                if (row0 < M)
                    *(float2*)(C + (size_t)row0 * N + col) = make_float2(v0, v1);
                if (row0 + 8 < M)
                    *(float2*)(C + (size_t)(row0 + 8) * N + col) = make_float2(v2, v3);
            }
        }
    }
}

// =====================================================================
// Tensor-core attention v3: 512 threads (16 warps), one block per (h,b).
// =====================================================================
#define ATT_NT     512
#define ATT_NW     16
#define ATT_K_OFF    0
#define ATT_V_OFF    52224
#define ATT_Q_OFF    107520
#define ATT_P_OFF    125952
#define ATT_S_OFF    144384
#define ATT_SSTRIDE  148
#define ATT_BIAS_OFF 172800
#define ATT_SMEM     173376

__global__ __launch_bounds__(ATT_NT) void attn_mma_kernel(
    const __half* __restrict__ qkv, const int* __restrict__ wvalid,
    __half* __restrict__ ctx_h)
{
    extern __shared__ char smemraw[];
    const unsigned sb = (unsigned)__cvta_generic_to_shared(smemraw);
    float* sS    = (float*)(smemraw + ATT_S_OFF);
    float* sBias = (float*)(smemraw + ATT_BIAS_OFF);

    const int h = blockIdx.x, b = blockIdx.y;
    const int tid = threadIdx.x;
    const int warp = tid >> 5, lane = tid & 31;

    const __half* kb = qkv + (size_t)b * Lwc * ROW3H + Hc + h * HDc;
    const __half* vb = kb + Hc;
    const __half* qb = qkv + (size_t)b * Lwc * ROW3H + h * HDc;

    // zero pad rows: K 129..135, V 129..143
    for (int i = tid; i < 22 * 24; i += ATT_NT) {
        int rr = i / 24, c = i - rr * 24;
        unsigned off = (rr < 7) ? (ATT_K_OFF + (129 + rr) * 384)
                                : (ATT_V_OFF + (129 + rr - 7) * 384);
        *(uint4*)(smemraw + off + c * 16) = make_uint4(0, 0, 0, 0);
    }
    // K + V via cp.async
    for (int i = tid; i < 2 * 129 * 24; i += ATT_NT) {
        int isV = (i >= 129 * 24);
        int j = isV ? i - 129 * 24 : i;
        int r = j / 24, c = j - r * 24;
        unsigned dst = sb + (isV ? ATT_V_OFF : ATT_K_OFF)
                     + r * 384 + ((c ^ (r & 7)) << 4);
        const __half* src = (isV ? vb : kb) + (size_t)r * ROW3H + c * 8;
        cp16(dst, src, 16u);
    }
    asm volatile("cp.async.commit_group;\n");
    for (int i = tid; i < 144; i += ATT_NT)
        sBias[i] = (i == 0) ? 0.f : ((i < Lwc && wvalid[b * Wc + i - 1]) ? 0.f : -1.0e30f);
    asm volatile("cp.async.wait_group 0;\n");
    __syncthreads();

    const int wr    = lane & 7;
    const int sel8  = (lane >> 3) & 1;
    const int sel16 = lane >> 4;
    const int fr    = lane >> 2;
    const int fc    = lane & 3;
    const unsigned aRow = (unsigned)((sel8 * 8 + wr) * 384);
    const float scale2 = SCALEc * LOG2Ec;

    for (int ch = 0; ch < 3; ch++) {
        const int q0 = ch * 48;
        const int nq = min(48, Lwc - q0);
        for (int i = tid; i < nq * 24; i += ATT_NT) {
            int r = i / 24, c = i - r * 24;
            cp16(sb + ATT_Q_OFF + r * 384 + ((c ^ (r & 7)) << 4),
                 qb + (size_t)(q0 + r) * ROW3H + c * 8, 16u);
        }
        asm volatile("cp.async.commit_group;\ncp.async.wait_group 0;\n");
        __syncthreads();

        // S = Q K^T : 51 tiles over 16 warps
        for (int idx = warp; idx < 51; idx += ATT_NW) {
            int mt = idx / 17, nt = idx - mt * 17;
            float acc[4] = {0.f, 0.f, 0.f, 0.f};
            unsigned aBase = sb + ATT_Q_OFF + mt * 6144 + aRow;
            unsigned bBase = sb + ATT_K_OFF + (nt * 8 + wr) * 384;
#pragma unroll
            for (int ks = 0; ks < 12; ks++) {
                unsigned a[4], bf[2];
                ldm4(a,  aBase + (((2 * ks + sel16) ^ wr) << 4));
                ldm2(bf, bBase + (((2 * ks + sel8) ^ wr) << 4));
                mma16(acc, a, bf[0], bf[1]);
            }
            int r0 = mt * 16 + fr, c0 = nt * 8 + 2 * fc;
            sS[r0 * ATT_SSTRIDE + c0]           = acc[0];
            sS[r0 * ATT_SSTRIDE + c0 + 1]       = acc[1];
            sS[(r0 + 8) * ATT_SSTRIDE + c0]     = acc[2];
            sS[(r0 + 8) * ATT_SSTRIDE + c0 + 1] = acc[3];
        }
        __syncthreads();

        // softmax (base-2) -> P fp16
        for (int r = warp; r < 48; r += ATT_NW) {
            float mx = -1e30f;
            for (int k = lane; k < Lwc; k += 32) {
                float v = sS[r * ATT_SSTRIDE + k] * scale2 + sBias[k];
                sS[r * ATT_SSTRIDE + k] = v;
                mx = fmaxf(mx, v);
            }
#pragma unroll
            for (int o = 16; o > 0; o >>= 1) mx = fmaxf(mx, __shfl_xor_sync(0xffffffffu, mx, o));
            float sum = 0.f;
            for (int k = lane; k < Lwc; k += 32) {
                float e = exp2f(sS[r * ATT_SSTRIDE + k] - mx);
                sS[r * ATT_SSTRIDE + k] = e;
                sum += e;
            }
#pragma unroll
            for (int o = 16; o > 0; o >>= 1) sum += __shfl_xor_sync(0xffffffffu, sum, o);
            float inv = 1.f / sum;
            for (int k = lane; k < 144; k += 32) {
                float p = (k < Lwc) ? sS[r * ATT_SSTRIDE + k] * inv : 0.f;
                int c = k >> 3, off = k & 7;
                *(__half*)(smemraw + ATT_P_OFF + r * 384 + ((c ^ (r & 7)) << 4) + off * 2) =
                    __float2half_rn(p);
            }
        }
        __syncthreads();

        // O = P V : 72 tiles over 16 warps; V row-major via ldmatrix.trans
        for (int idx = warp; idx < 72; idx += ATT_NW) {
            int mt = idx / 24, nt = idx - mt * 24;
            float acc[4] = {0.f, 0.f, 0.f, 0.f};
            unsigned aBase = sb + ATT_P_OFF + mt * 6144 + aRow;
            const unsigned vRow = (sel8 * 8 + wr) * 384;
            const unsigned vChunk = ((unsigned)(nt ^ wr)) << 4;
#pragma unroll
            for (int ks = 0; ks < 9; ks++) {
                unsigned a[4], bf[2];
                ldm4(a, aBase + (((2 * ks + sel16) ^ wr) << 4));
                ldm2t(bf, sb + ATT_V_OFF + ks * 6144 + vRow + vChunk);
                mma16(acc, a, bf[0], bf[1]);
            }
            int rloc = mt * 16 + fr;
            int d = nt * 8 + 2 * fc;
            if (rloc < nq)
                *(__half2*)(ctx_h + (size_t)(b * Lwc + q0 + rloc) * Hc + h * HDc + d) =
                    __floats2half2_rn(acc[0], acc[1]);
            if (rloc + 8 < nq)
                *(__half2*)(ctx_h + (size_t)(b * Lwc + q0 + rloc + 8) * Hc + h * HDc + d) =
                    __floats2half2_rn(acc[2], acc[3]);
        }
        __syncthreads();
    }
}

// ---------------- residual add + layernorm: one warp per row, float4 ----------------
__global__ __launch_bounds__(256) void add_ln_kernel(
    const float* __restrict__ base, const float* __restrict__ delta,
    const float* __restrict__ sc, const float* __restrict__ bi,
    float* __restrict__ out, __half* __restrict__ out_h)
{
    const int row = blockIdx.x * 8 + (threadIdx.x >> 5);
    const int lane = threadIdx.x & 31;
    if (row >= Mc) return;
    const float4* xb = (const float4*)(base + (size_t)row * Hc);
    const float4* db = (const float4*)(delta + (size_t)row * Hc);
    float4 v[6];
    float s = 0.f, ss = 0.f;
#pragma unroll
    for (int i = 0; i < 6; i++) {
        int j = lane + i * 32;
        float4 a = xb[j], d = db[j];
        a.x += d.x; a.y += d.y; a.z += d.z; a.w += d.w;
        v[i] = a;
        s  += a.x + a.y + a.z + a.w;
        ss += a.x * a.x + a.y * a.y + a.z * a.z + a.w * a.w;
    }
#pragma unroll
    for (int o = 16; o > 0; o >>= 1) {
        s  += __shfl_xor_sync(0xffffffffu, s, o);
        ss += __shfl_xor_sync(0xffffffffu, ss, o);
    }
    float mean = s * (1.f / Hc);
    float var  = ss * (1.f / Hc) - mean * mean;
    float r = rsqrtf(var + EPSc);
    float4* op = (float4*)(out + (size_t)row * Hc);
    uint2*  oh = (uint2*)(out_h + (size_t)row * Hc);
    const float4* scp = (const float4*)sc;
    const float4* bip = (const float4*)bi;
#pragma unroll
    for (int i = 0; i < 6; i++) {
        int j = lane + i * 32;
        float4 sv = scp[j], bv = bip[j];
        float4 o;
        o.x = (v[i].x - mean) * r * sv.x + bv.x;
        o.y = (v[i].y - mean) * r * sv.y + bv.y;
        o.z = (v[i].z - mean) * r * sv.z + bv.z;
        o.w = (v[i].w - mean) * r * sv.w + bv.w;
        op[j] = o;
        __half2 h0 = __floats2half2_rn(o.x, o.y);
        __half2 h1 = __floats2half2_rn(o.z, o.w);
        oh[j] = make_uint2(*(unsigned*)&h0, *(unsigned*)&h1);
    }
}

// ---------------- classifier + pooled output ----------------
__global__ __launch_bounds__(256) void cls_kernel(
    const float* __restrict__ x, const float* __restrict__ cw,
    const float* __restrict__ cb, float* __restrict__ out)
{
    int b = blockIdx.x, t = threadIdx.x;
    const float* p = x + (size_t)(b * Lwc) * Hc;
    for (int j = t; j < Hc; j += 256) out[Bc * NLABc + b * Hc + j] = p[j];
    int wid = t >> 5, lane = t & 31;
    if (wid < NLABc) {
        float s = 0.f;
        for (int j = lane; j < Hc; j += 32) s += p[j] * cw[wid * Hc + j];
#pragma unroll
        for (int o = 16; o > 0; o >>= 1) s += __shfl_down_sync(0xffffffffu, s, o);
        if (lane == 0) out[b * NLABc + wid] = s + cb[wid];
    }
}

// ---------------- host ----------------
template <typename T>
static T* symaddr(const void* sym) {
    void* p = nullptr;
    cudaGetSymbolAddress(&p, sym);
    return (T*)p;
}

extern "C" void kernel_launch(void* const* d_in, const int* in_sizes, int n_in,
                              void* d_out, int out_size)
{
    const float* hidden = (const float*)d_in[0];
    const int*   wti    = (const int*)  d_in[1];
    const int*   gmask  = (const int*)  d_in[2];
    const int*   wvalid = (const int*)  d_in[3];
    const float* qkv_w  = (const float*)d_in[4];
    const float* qkv_b  = (const float*)d_in[5];
    const float* out_w  = (const float*)d_in[6];
    const float* out_b  = (const float*)d_in[7];
    const float* ff1_w  = (const float*)d_in[8];
    const float* ff1_b  = (const float*)d_in[9];
    const float* ff2_w  = (const float*)d_in[10];
    const float* ff2_b  = (const float*)d_in[11];
    const float* ln1_s  = (const float*)d_in[12];
    const float* ln1_b  = (const float*)d_in[13];
    const float* ln2_s  = (const float*)d_in[14];
    const float* ln2_b  = (const float*)d_in[15];
    const float* cls_w  = (const float*)d_in[16];
    const float* cls_b  = (const float*)d_in[17];
    float* out = (float*)d_out;

    float*  x     = symaddr<float>(g_x);
    __half* x_h   = symaddr<__half>(g_x_h);
    __half* qkv_h = symaddr<__half>(g_qkv_h);
    __half* ctx_h = symaddr<__half>(g_ctx_h);
    float*  y     = symaddr<float>(g_y);
    __half* ff_h  = symaddr<__half>(g_ff_h);
    __half* qkvw_h = symaddr<__half>(g_qkvw_h);
    __half* outw_h = symaddr<__half>(g_outw_h);
    __half* ff1w_h = symaddr<__half>(g_ff1w_h);
    __half* ff2w_h = symaddr<__half>(g_ff2w_h);

    static bool attr_done = false;
    if (!attr_done) {
        cudaFuncSetAttribute(gemm_f16_async<0>, cudaFuncAttributeMaxDynamicSharedMemorySize,
                             GEMM_SMEM);
        cudaFuncSetAttribute(gemm_f16_async<1>, cudaFuncAttributeMaxDynamicSharedMemorySize,
                             GEMM_SMEM);
        cudaFuncSetAttribute(gemm_f16_async<2>, cudaFuncAttributeMaxDynamicSharedMemorySize,
                             GEMM_SMEM);
        cudaFuncSetAttribute(attn_mma_kernel, cudaFuncAttributeMaxDynamicSharedMemorySize,
                             ATT_SMEM);
        attr_done = true;
    }

    cvt_all_kernel<<<256, 256>>>(
        (const float4*)qkv_w, (const float4*)out_w,
        (const float4*)ff1_w, (const float4*)ff2_w,
        (uint4*)qkvw_h, (uint4*)outw_h, (uint4*)ff1w_h, (uint4*)ff2w_h);

    build_x_kernel<<<dim3(Lwc, Bc), 256>>>(hidden, wti, gmask, wvalid, x, x_h);

    const int MB = (Mc + BMt - 1) / BMt;     // 33
    dim3 gQKV(3 * Hc / BNt, MB);
    dim3 gH  (Hc / BNt,     MB);
    dim3 gFF (FFc / BNt,    MB);
    const int lnGrid = (Mc + 7) / 8;         // 516

    for (int l = 0; l < NLc; l++) {
        gemm_f16_async<2><<<gQKV, 256, GEMM_SMEM>>>(
            x_h, qkvw_h + (size_t)l * 3 * Hc * Hc,
            qkv_b + (size_t)l * 3 * Hc, qkv_h, Mc, 3 * Hc, Hc);
        attn_mma_kernel<<<dim3(NHc, Bc), ATT_NT, ATT_SMEM>>>(qkv_h, wvalid, ctx_h);
        gemm_f16_async<0><<<gH, 256, GEMM_SMEM>>>(
            ctx_h, outw_h + (size_t)l * Hc * Hc,
            out_b + (size_t)l * Hc, y, Mc, Hc, Hc);
        add_ln_kernel<<<lnGrid, 256>>>(x, y, ln1_s + (size_t)l * Hc, ln1_b + (size_t)l * Hc, x, x_h);
        gemm_f16_async<1><<<gFF, 256, GEMM_SMEM>>>(
            x_h, ff1w_h + (size_t)l * FFc * Hc,
            ff1_b + (size_t)l * FFc, ff_h, Mc, FFc, Hc);
        gemm_f16_async<0><<<gH, 256, GEMM_SMEM>>>(
            ff_h, ff2w_h + (size_t)l * Hc * FFc,
            ff2_b + (size_t)l * Hc, y, Mc, Hc, FFc);
        add_ln_kernel<<<lnGrid, 256>>>(x, y, ln2_s + (size_t)l * Hc, ln2_b + (size_t)l * Hc, x, x_h);
    }

    cls_kernel<<<Bc, 256>>>(x, cls_w, cls_b, out);
}

// round 17
// speedup vs baseline: 17.1826x; 1.0261x over previous
#include <cuda_runtime.h>
#include <cuda_fp16.h>
#include <math.h>

// ---------------- problem constants ----------------
#define Bc    32
#define Sc    512
#define Hc    768
#define Wc    128
#define Gc    4
#define NHc   4
#define HDc   192
#define FFc   2048
#define NLc   2
#define NLABc 6
#define Lwc   (Wc + 1)          // 129
#define Mc    (Bc * Lwc)        // 4128
#define EPSc  1e-5f
#define SCALEc 0.07216878364870322f  // 1/sqrt(192)
#define LOG2Ec 1.4426950408889634f
#define ROW3H (3 * Hc)

// ---------------- scratch (device globals; no allocs) ----------------
__device__ float  g_x   [Mc * Hc];
__device__ __half g_x_h [Mc * Hc];
__device__ __half g_qkv_h[Mc * ROW3H];
__device__ __half g_ctx_h[Mc * Hc];
__device__ float  g_y   [Mc * Hc];
__device__ __half g_ff_h[Mc * FFc];
__device__ __half g_qkvw_h[NLc * 3 * Hc * Hc];
__device__ __half g_outw_h[NLc * Hc * Hc];
__device__ __half g_ff1w_h[NLc * FFc * Hc];
__device__ __half g_ff2w_h[NLc * Hc * FFc];

// ---------------- prep kernel: weight cvt + build_x merged ----------------
#define CVN1 442368
#define CVN2 147456
#define CVN3 393216
#define CVN4 393216
#define CVT_TOT (CVN1 + CVN2 + CVN3 + CVN4)
#define CVT_BLOCKS 256
#define PREP_GRID (Mc + CVT_BLOCKS)        // 4128 build_x blocks + 256 cvt blocks

__global__ __launch_bounds__(256) void prep_kernel(
    const float* __restrict__ hidden, const int* __restrict__ wti,
    const int* __restrict__ gmask, const int* __restrict__ wvalid,
    float* __restrict__ x, __half* __restrict__ x_h,
    const float4* __restrict__ w1, const float4* __restrict__ w2,
    const float4* __restrict__ w3, const float4* __restrict__ w4,
    uint4* __restrict__ o1, uint4* __restrict__ o2,
    uint4* __restrict__ o3, uint4* __restrict__ o4)
{
    const int bx = blockIdx.x;
    const int t = threadIdx.x;
    if (bx >= Mc) {
        // ---- weight conversion part ----
        int i = (bx - Mc) * 256 + t;
        const int stride = CVT_BLOCKS * 256;
        for (; i < CVT_TOT; i += stride) {
            const float4* src; uint4* dst; int j;
            if (i < CVN1)                    { src = w1; dst = o1; j = i; }
            else if (i < CVN1 + CVN2)        { src = w2; dst = o2; j = i - CVN1; }
            else if (i < CVN1 + CVN2 + CVN3) { src = w3; dst = o3; j = i - CVN1 - CVN2; }
            else                             { src = w4; dst = o4; j = i - CVN1 - CVN2 - CVN3; }
            float4 a = src[2 * j], b = src[2 * j + 1];
            __half2 h0 = __floats2half2_rn(a.x, a.y);
            __half2 h1 = __floats2half2_rn(a.z, a.w);
            __half2 h2 = __floats2half2_rn(b.x, b.y);
            __half2 h3 = __floats2half2_rn(b.z, b.w);
            uint4 o;
            o.x = *(unsigned*)&h0; o.y = *(unsigned*)&h1;
            o.z = *(unsigned*)&h2; o.w = *(unsigned*)&h3;
            dst[j] = o;
        }
        return;
    }
    // ---- build_x part ----
    const int w = bx % Lwc, b = bx / Lwc;
    size_t ro = (size_t)(b * Lwc + w) * Hc;
    if (w == 0) {
        const float* hr = hidden + (size_t)(b * Sc) * Hc;
        for (int j = t; j < Hc; j += 256) {
            float v = hr[j]; x[ro + j] = v; x_h[ro + j] = __float2half_rn(v);
        }
        return;
    }
    int wi = w - 1;
    int valid = wvalid[b * Wc + wi];
    const float* hrows[Gc];
    float m[Gc];
    float cnt = 0.f;
#pragma unroll
    for (int g = 0; g < Gc; g++) {
        int idx = wti[(b * Wc + wi) * Gc + g];
        hrows[g] = hidden + (size_t)(b * Sc + idx) * Hc;
        m[g] = gmask[(b * Wc + wi) * Gc + g] ? 1.f : 0.f;
        cnt += m[g];
    }
    float inv = valid ? (1.f / fmaxf(cnt, 1.f)) : 0.f;
    for (int j = t; j < Hc; j += 256) {
        float s = 0.f;
#pragma unroll
        for (int g = 0; g < Gc; g++) s += m[g] * hrows[g][j];
        float v = s * inv;
        x[ro + j] = v; x_h[ro + j] = __float2half_rn(v);
    }
}

// ---------------- shared mma helpers ----------------
__device__ __forceinline__ void ldm4(unsigned* r, unsigned addr) {
    asm volatile("ldmatrix.sync.aligned.m8n8.x4.shared.b16 {%0,%1,%2,%3}, [%4];"
                 : "=r"(r[0]), "=r"(r[1]), "=r"(r[2]), "=r"(r[3]) : "r"(addr));
}
__device__ __forceinline__ void ldm2(unsigned* r, unsigned addr) {
    asm volatile("ldmatrix.sync.aligned.m8n8.x2.shared.b16 {%0,%1}, [%2];"
                 : "=r"(r[0]), "=r"(r[1]) : "r"(addr));
}
__device__ __forceinline__ void ldm2t(unsigned* r, unsigned addr) {
    asm volatile("ldmatrix.sync.aligned.m8n8.x2.trans.shared.b16 {%0,%1}, [%2];"
                 : "=r"(r[0]), "=r"(r[1]) : "r"(addr));
}
__device__ __forceinline__ void mma16(float* d, const unsigned* a, unsigned b0, unsigned b1) {
    asm volatile(
        "mma.sync.aligned.m16n8k16.row.col.f32.f16.f16.f32 "
        "{%0,%1,%2,%3}, {%4,%5,%6,%7}, {%8,%9}, {%0,%1,%2,%3};\n"
        : "+f"(d[0]), "+f"(d[1]), "+f"(d[2]), "+f"(d[3])
        : "r"(a[0]), "r"(a[1]), "r"(a[2]), "r"(a[3]), "r"(b0), "r"(b1));
}
__device__ __forceinline__ void cp16(unsigned dst, const void* src, unsigned sz) {
    asm volatile("cp.async.cg.shared.global [%0], [%1], 16, %2;\n"
                 :: "r"(dst), "l"(src), "r"(sz));
}

// =====================================================================
// FP16 tensor-core GEMM.  MODE 0: fp32 out. 1: relu+fp16. 2: fp16.
// =====================================================================
#define BMt 128
#define BNt 128
#define BKt 64
#define STAGES 3
#define SA_BYTES 16384
#define SB_OFF   (STAGES * SA_BYTES)
#define GEMM_SMEM (2 * STAGES * SA_BYTES)

template <int MODE>
__global__ __launch_bounds__(256, 2) void gemm_f16_async(
    const __half* __restrict__ A, const __half* __restrict__ B,
    const float* __restrict__ bias, void* __restrict__ Cout,
    int M, int N, int K)
{
    extern __shared__ char gsm[];
    const unsigned sbase = (unsigned)__cvta_generic_to_shared(gsm);

    const int tid  = threadIdx.x;
    const int warp = tid >> 5;
    const int lane = tid & 31;
    const int wm = warp >> 2;
    const int wn = warp & 3;
    const int rowBase = blockIdx.y * BMt;
    const int colBase = blockIdx.x * BNt;

    const int cc = tid & 7;
    const int cr = tid >> 3;
    const __half* aSrc[4];
    const __half* bSrc[4];
    unsigned aSz[4];
    unsigned dA[4], dB[4];
#pragma unroll
    for (int j = 0; j < 4; j++) {
        int r = cr + 32 * j;
        int grow = rowBase + r;
        aSrc[j] = A + (size_t)grow * K + cc * 8;
        aSz[j]  = (grow < M) ? 16u : 0u;
        bSrc[j] = B + (size_t)(colBase + r) * K + cc * 8;
        unsigned d = r * 128 + ((cc ^ (r & 7)) << 4);
        dA[j] = sbase + d;
        dB[j] = sbase + SB_OFF + d;
    }

    const int wr     = lane & 7;
    const int rowOff = ((lane >> 3) & 1) * 8 + wr;
    const int cAdd   = lane >> 4;
    const unsigned aFragBase = (wm * 64 + rowOff) * 128;
    const unsigned bFragBase = SB_OFF + (wn * 32 + rowOff) * 128;
    unsigned swz[4];
#pragma unroll
    for (int ks = 0; ks < 4; ks++)
        swz[ks] = ((unsigned)((2 * ks + cAdd) ^ wr)) << 4;

    float acc[4][4][4];
#pragma unroll
    for (int i = 0; i < 4; i++)
#pragma unroll
        for (int j = 0; j < 4; j++)
#pragma unroll
            for (int q = 0; q < 4; q++) acc[i][j][q] = 0.f;

    const int nk = K / BKt;

#pragma unroll
    for (int s = 0; s < 2; s++) {
        const int k0 = s * BKt;
        const unsigned so = s * SA_BYTES;
#pragma unroll
        for (int j = 0; j < 4; j++) cp16(dA[j] + so, aSrc[j] + k0, aSz[j]);
#pragma unroll
        for (int j = 0; j < 4; j++) cp16(dB[j] + so, bSrc[j] + k0, 16u);
        asm volatile("cp.async.commit_group;\n");
    }

#pragma unroll 3
    for (int t = 0; t < nk; t++) {
        asm volatile("cp.async.wait_group 1;\n");
        __syncthreads();
        if (t + 2 < nk) {
            const int s = (t + 2) % STAGES;
            const int k0 = (t + 2) * BKt;
            const unsigned so = s * SA_BYTES;
#pragma unroll
            for (int j = 0; j < 4; j++) cp16(dA[j] + so, aSrc[j] + k0, aSz[j]);
#pragma unroll
            for (int j = 0; j < 4; j++) cp16(dB[j] + so, bSrc[j] + k0, 16u);
        }
        asm volatile("cp.async.commit_group;\n");

        const unsigned stOff = (t % STAGES) * SA_BYTES;
#pragma unroll
        for (int ks = 0; ks < 4; ks++) {
            const unsigned so = swz[ks] + stOff;
            unsigned af[4][4];
#pragma unroll
            for (int mt = 0; mt < 4; mt++)
                ldm4(af[mt], sbase + aFragBase + mt * 2048 + so);
            unsigned bf[2][4];
#pragma unroll
            for (int ntp = 0; ntp < 2; ntp++)
                ldm4(bf[ntp], sbase + bFragBase + ntp * 2048 + so);
#pragma unroll
            for (int mt = 0; mt < 4; mt++)
#pragma unroll
                for (int ntp = 0; ntp < 2; ntp++)
#pragma unroll
                    for (int ntl = 0; ntl < 2; ntl++)
                        mma16(acc[mt][ntp * 2 + ntl], af[mt],
                              bf[ntp][ntl], bf[ntp][2 + ntl]);
        }
    }

    const int fr = lane >> 2;
    const int fc = lane & 3;
#pragma unroll
    for (int mt = 0; mt < 4; mt++) {
        int row0 = rowBase + wm * 64 + mt * 16 + fr;
#pragma unroll
        for (int nt = 0; nt < 4; nt++) {
            int col = colBase + wn * 32 + nt * 8 + 2 * fc;
            float b0 = bias[col], b1 = bias[col + 1];
            float v0 = acc[mt][nt][0] + b0;
            float v1 = acc[mt][nt][1] + b1;
            float v2 = acc[mt][nt][2] + b0;
            float v3 = acc[mt][nt][3] + b1;
            if (MODE >= 1) {
                if (MODE == 1) {
                    v0 = fmaxf(v0, 0.f); v1 = fmaxf(v1, 0.f);
                    v2 = fmaxf(v2, 0.f); v3 = fmaxf(v3, 0.f);
                }
                __half2* C = (__half2*)Cout;
                if (row0 < M)
                    C[((size_t)row0 * N + col) >> 1] = __floats2half2_rn(v0, v1);
                if (row0 + 8 < M)
                    C[((size_t)(row0 + 8) * N + col) >> 1] = __floats2half2_rn(v2, v3);
            } else {
                float* C = (float*)Cout;
                if (row0 < M)
                    *(float2*)(C + (size_t)row0 * N + col) = make_float2(v0, v1);
                if (row0 + 8 < M)
                    *(float2*)(C + (size_t)(row0 + 8) * N + col) = make_float2(v2, v3);
            }
        }
    }
}

// =====================================================================
// Tensor-core attention v4: 768 threads (24 warps), Q-chunk prefetch.
// =====================================================================
#define ATT_NT     768
#define ATT_NW     24
#define ATT_K_OFF    0
#define ATT_V_OFF    52224
#define ATT_Q_OFF    107520
#define ATT_P_OFF    125952
#define ATT_S_OFF    144384
#define ATT_SSTRIDE  148
#define ATT_BIAS_OFF 172800
#define ATT_SMEM     173376

__global__ __launch_bounds__(ATT_NT) void attn_mma_kernel(
    const __half* __restrict__ qkv, const int* __restrict__ wvalid,
    __half* __restrict__ ctx_h)
{
    extern __shared__ char smemraw[];
    const unsigned sb = (unsigned)__cvta_generic_to_shared(smemraw);
    float* sS    = (float*)(smemraw + ATT_S_OFF);
    float* sBias = (float*)(smemraw + ATT_BIAS_OFF);

    const int h = blockIdx.x, b = blockIdx.y;
    const int tid = threadIdx.x;
    const int warp = tid >> 5, lane = tid & 31;

    const __half* kb = qkv + (size_t)b * Lwc * ROW3H + Hc + h * HDc;
    const __half* vb = kb + Hc;
    const __half* qb = qkv + (size_t)b * Lwc * ROW3H + h * HDc;

    // zero pad rows: K 129..135, V 129..143
    for (int i = tid; i < 22 * 24; i += ATT_NT) {
        int rr = i / 24, c = i - rr * 24;
        unsigned off = (rr < 7) ? (ATT_K_OFF + (129 + rr) * 384)
                                : (ATT_V_OFF + (129 + rr - 7) * 384);
        *(uint4*)(smemraw + off + c * 16) = make_uint4(0, 0, 0, 0);
    }
    // K + V + Q(chunk 0) via cp.async
    for (int i = tid; i < 2 * 129 * 24; i += ATT_NT) {
        int isV = (i >= 129 * 24);
        int j = isV ? i - 129 * 24 : i;
        int r = j / 24, c = j - r * 24;
        unsigned dst = sb + (isV ? ATT_V_OFF : ATT_K_OFF)
                     + r * 384 + ((c ^ (r & 7)) << 4);
        const __half* src = (isV ? vb : kb) + (size_t)r * ROW3H + c * 8;
        cp16(dst, src, 16u);
    }
    for (int i = tid; i < 48 * 24; i += ATT_NT) {
        int r = i / 24, c = i - r * 24;
        cp16(sb + ATT_Q_OFF + r * 384 + ((c ^ (r & 7)) << 4),
             qb + (size_t)r * ROW3H + c * 8, 16u);
    }
    asm volatile("cp.async.commit_group;\n");
    for (int i = tid; i < 144; i += ATT_NT)
        sBias[i] = (i == 0) ? 0.f : ((i < Lwc && wvalid[b * Wc + i - 1]) ? 0.f : -1.0e30f);
    asm volatile("cp.async.wait_group 0;\n");
    __syncthreads();

    const int wr    = lane & 7;
    const int sel8  = (lane >> 3) & 1;
    const int sel16 = lane >> 4;
    const int fr    = lane >> 2;
    const int fc    = lane & 3;
    const unsigned aRow = (unsigned)((sel8 * 8 + wr) * 384);
    const float scale2 = SCALEc * LOG2Ec;

    for (int ch = 0; ch < 3; ch++) {
        const int q0 = ch * 48;
        const int nq = min(48, Lwc - q0);

        // S = Q K^T : 51 tiles over 24 warps
        for (int idx = warp; idx < 51; idx += ATT_NW) {
            int mt = idx / 17, nt = idx - mt * 17;
            float acc[4] = {0.f, 0.f, 0.f, 0.f};
            unsigned aBase = sb + ATT_Q_OFF + mt * 6144 + aRow;
            unsigned bBase = sb + ATT_K_OFF + (nt * 8 + wr) * 384;
#pragma unroll
            for (int ks = 0; ks < 12; ks++) {
                unsigned a[4], bf[2];
                ldm4(a,  aBase + (((2 * ks + sel16) ^ wr) << 4));
                ldm2(bf, bBase + (((2 * ks + sel8) ^ wr) << 4));
                mma16(acc, a, bf[0], bf[1]);
            }
            int r0 = mt * 16 + fr, c0 = nt * 8 + 2 * fc;
            sS[r0 * ATT_SSTRIDE + c0]           = acc[0];
            sS[r0 * ATT_SSTRIDE + c0 + 1]       = acc[1];
            sS[(r0 + 8) * ATT_SSTRIDE + c0]     = acc[2];
            sS[(r0 + 8) * ATT_SSTRIDE + c0 + 1] = acc[3];
        }
        __syncthreads();

        // prefetch next Q chunk (Q buffer is idle during softmax/O)
        if (ch + 1 < 3) {
            const int q1 = (ch + 1) * 48;
            const int nq1 = min(48, Lwc - q1);
            for (int i = tid; i < nq1 * 24; i += ATT_NT) {
                int r = i / 24, c = i - r * 24;
                cp16(sb + ATT_Q_OFF + r * 384 + ((c ^ (r & 7)) << 4),
                     qb + (size_t)(q1 + r) * ROW3H + c * 8, 16u);
            }
        }
        asm volatile("cp.async.commit_group;\n");

        // softmax (base-2) -> P fp16
        for (int r = warp; r < 48; r += ATT_NW) {
            float mx = -1e30f;
            for (int k = lane; k < Lwc; k += 32) {
                float v = sS[r * ATT_SSTRIDE + k] * scale2 + sBias[k];
                sS[r * ATT_SSTRIDE + k] = v;
                mx = fmaxf(mx, v);
            }
#pragma unroll
            for (int o = 16; o > 0; o >>= 1) mx = fmaxf(mx, __shfl_xor_sync(0xffffffffu, mx, o));
            float sum = 0.f;
            for (int k = lane; k < Lwc; k += 32) {
                float e = exp2f(sS[r * ATT_SSTRIDE + k] - mx);
                sS[r * ATT_SSTRIDE + k] = e;
                sum += e;
            }
#pragma unroll
            for (int o = 16; o > 0; o >>= 1) sum += __shfl_xor_sync(0xffffffffu, sum, o);
            float inv = 1.f / sum;
            for (int k = lane; k < 144; k += 32) {
                float p = (k < Lwc) ? sS[r * ATT_SSTRIDE + k] * inv : 0.f;
                int c = k >> 3, off = k & 7;
                *(__half*)(smemraw + ATT_P_OFF + r * 384 + ((c ^ (r & 7)) << 4) + off * 2) =
                    __float2half_rn(p);
            }
        }
        __syncthreads();

        // O = P V : 72 tiles over 24 warps; V row-major via ldmatrix.trans
        for (int idx = warp; idx < 72; idx += ATT_NW) {
            int mt = idx / 24, nt = idx - mt * 24;
            float acc[4] = {0.f, 0.f, 0.f, 0.f};
            unsigned aBase = sb + ATT_P_OFF + mt * 6144 + aRow;
            const unsigned vRow = (sel8 * 8 + wr) * 384;
            const unsigned vChunk = ((unsigned)(nt ^ wr)) << 4;
#pragma unroll
            for (int ks = 0; ks < 9; ks++) {
                unsigned a[4], bf[2];
                ldm4(a, aBase + (((2 * ks + sel16) ^ wr) << 4));
                ldm2t(bf, sb + ATT_V_OFF + ks * 6144 + vRow + vChunk);
                mma16(acc, a, bf[0], bf[1]);
            }
            int rloc = mt * 16 + fr;
            int d = nt * 8 + 2 * fc;
            if (rloc < nq)
                *(__half2*)(ctx_h + (size_t)(b * Lwc + q0 + rloc) * Hc + h * HDc + d) =
                    __floats2half2_rn(acc[0], acc[1]);
            if (rloc + 8 < nq)
                *(__half2*)(ctx_h + (size_t)(b * Lwc + q0 + rloc + 8) * Hc + h * HDc + d) =
                    __floats2half2_rn(acc[2], acc[3]);
        }
        asm volatile("cp.async.wait_group 0;\n");
        __syncthreads();
    }
}

// ---------------- residual add + layernorm (+ optional classifier) ----------------
// One warp per row, float4. DOCLS: rows with row%Lwc==0 also emit logits+pooled.
template <bool DOCLS>
__global__ __launch_bounds__(256) void add_ln_kernel(
    const float* __restrict__ base, const float* __restrict__ delta,
    const float* __restrict__ sc, const float* __restrict__ bi,
    float* __restrict__ out, __half* __restrict__ out_h,
    const float* __restrict__ cw, const float* __restrict__ cb,
    float* __restrict__ clsout)
{
    const int row = blockIdx.x * 8 + (threadIdx.x >> 5);
    const int lane = threadIdx.x & 31;
    if (row >= Mc) return;
    const float4* xb = (const float4*)(base + (size_t)row * Hc);
    const float4* db = (const float4*)(delta + (size_t)row * Hc);
    float4 v[6];
    float s = 0.f, ss = 0.f;
#pragma unroll
    for (int i = 0; i < 6; i++) {
        int j = lane + i * 32;
        float4 a = xb[j], d = db[j];
        a.x += d.x; a.y += d.y; a.z += d.z; a.w += d.w;
        v[i] = a;
        s  += a.x + a.y + a.z + a.w;
        ss += a.x * a.x + a.y * a.y + a.z * a.z + a.w * a.w;
    }
#pragma unroll
    for (int o = 16; o > 0; o >>= 1) {
        s  += __shfl_xor_sync(0xffffffffu, s, o);
        ss += __shfl_xor_sync(0xffffffffu, ss, o);
    }
    float mean = s * (1.f / Hc);
    float var  = ss * (1.f / Hc) - mean * mean;
    float r = rsqrtf(var + EPSc);
    float4* op = (float4*)(out + (size_t)row * Hc);
    uint2*  oh = (uint2*)(out_h + (size_t)row * Hc);
    const float4* scp = (const float4*)sc;
    const float4* bip = (const float4*)bi;
    float4 ov[6];
#pragma unroll
    for (int i = 0; i < 6; i++) {
        int j = lane + i * 32;
        float4 sv = scp[j], bv = bip[j];
        float4 o;
        o.x = (v[i].x - mean) * r * sv.x + bv.x;
        o.y = (v[i].y - mean) * r * sv.y + bv.y;
        o.z = (v[i].z - mean) * r * sv.z + bv.z;
        o.w = (v[i].w - mean) * r * sv.w + bv.w;
        ov[i] = o;
        op[j] = o;
        __half2 h0 = __floats2half2_rn(o.x, o.y);
        __half2 h1 = __floats2half2_rn(o.z, o.w);
        oh[j] = make_uint2(*(unsigned*)&h0, *(unsigned*)&h1);
    }
    if (DOCLS && (row % Lwc == 0)) {
        const int bidx = row / Lwc;
        // pooled
        float4* pp = (float4*)(clsout + Bc * NLABc + (size_t)bidx * Hc);
#pragma unroll
        for (int i = 0; i < 6; i++) pp[lane + i * 32] = ov[i];
        // logits
        const float4* cwp = (const float4*)cw;
#pragma unroll
        for (int lab = 0; lab < NLABc; lab++) {
            float acc = 0.f;
#pragma unroll
            for (int i = 0; i < 6; i++) {
                int j = lane + i * 32;
                float4 wv = cwp[lab * (Hc / 4) + j];
                acc += ov[i].x * wv.x + ov[i].y * wv.y + ov[i].z * wv.z + ov[i].w * wv.w;
            }
#pragma unroll
            for (int o = 16; o > 0; o >>= 1) acc += __shfl_xor_sync(0xffffffffu, acc, o);
            if (lane == 0) clsout[bidx * NLABc + lab] = acc + cb[lab];
        }
    }
}

// ---------------- host ----------------
template <typename T>
static T* symaddr(const void* sym) {
    void* p = nullptr;
    cudaGetSymbolAddress(&p, sym);
    return (T*)p;
}

extern "C" void kernel_launch(void* const* d_in, const int* in_sizes, int n_in,
                              void* d_out, int out_size)
{
    const float* hidden = (const float*)d_in[0];
    const int*   wti    = (const int*)  d_in[1];
    const int*   gmask  = (const int*)  d_in[2];
    const int*   wvalid = (const int*)  d_in[3];
    const float* qkv_w  = (const float*)d_in[4];
    const float* qkv_b  = (const float*)d_in[5];
    const float* out_w  = (const float*)d_in[6];
    const float* out_b  = (const float*)d_in[7];
    const float* ff1_w  = (const float*)d_in[8];
    const float* ff1_b  = (const float*)d_in[9];
    const float* ff2_w  = (const float*)d_in[10];
    const float* ff2_b  = (const float*)d_in[11];
    const float* ln1_s  = (const float*)d_in[12];
    const float* ln1_b  = (const float*)d_in[13];
    const float* ln2_s  = (const float*)d_in[14];
    const float* ln2_b  = (const float*)d_in[15];
    const float* cls_w  = (const float*)d_in[16];
    const float* cls_b  = (const float*)d_in[17];
    float* out = (float*)d_out;

    float*  x     = symaddr<float>(g_x);
    __half* x_h   = symaddr<__half>(g_x_h);
    __half* qkv_h = symaddr<__half>(g_qkv_h);
    __half* ctx_h = symaddr<__half>(g_ctx_h);
    float*  y     = symaddr<float>(g_y);
    __half* ff_h  = symaddr<__half>(g_ff_h);
    __half* qkvw_h = symaddr<__half>(g_qkvw_h);
    __half* outw_h = symaddr<__half>(g_outw_h);
    __half* ff1w_h = symaddr<__half>(g_ff1w_h);
    __half* ff2w_h = symaddr<__half>(g_ff2w_h);

    static bool attr_done = false;
    if (!attr_done) {
        cudaFuncSetAttribute(gemm_f16_async<0>, cudaFuncAttributeMaxDynamicSharedMemorySize,
                             GEMM_SMEM);
        cudaFuncSetAttribute(gemm_f16_async<1>, cudaFuncAttributeMaxDynamicSharedMemorySize,
                             GEMM_SMEM);
        cudaFuncSetAttribute(gemm_f16_async<2>, cudaFuncAttributeMaxDynamicSharedMemorySize,
                             GEMM_SMEM);
        cudaFuncSetAttribute(attn_mma_kernel, cudaFuncAttributeMaxDynamicSharedMemorySize,
                             ATT_SMEM);
        attr_done = true;
    }

    prep_kernel<<<PREP_GRID, 256>>>(
        hidden, wti, gmask, wvalid, x, x_h,
        (const float4*)qkv_w, (const float4*)out_w,
        (const float4*)ff1_w, (const float4*)ff2_w,
        (uint4*)qkvw_h, (uint4*)outw_h, (uint4*)ff1w_h, (uint4*)ff2w_h);

    const int MB = (Mc + BMt - 1) / BMt;     // 33
    dim3 gQKV(3 * Hc / BNt, MB);
    dim3 gH  (Hc / BNt,     MB);
    dim3 gFF (FFc / BNt,    MB);
    const int lnGrid = (Mc + 7) / 8;         // 516

    for (int l = 0; l < NLc; l++) {
        gemm_f16_async<2><<<gQKV, 256, GEMM_SMEM>>>(
            x_h, qkvw_h + (size_t)l * 3 * Hc * Hc,
            qkv_b + (size_t)l * 3 * Hc, qkv_h, Mc, 3 * Hc, Hc);
        attn_mma_kernel<<<dim3(NHc, Bc), ATT_NT, ATT_SMEM>>>(qkv_h, wvalid, ctx_h);
        gemm_f16_async<0><<<gH, 256, GEMM_SMEM>>>(
            ctx_h, outw_h + (size_t)l * Hc * Hc,
            out_b + (size_t)l * Hc, y, Mc, Hc, Hc);
        add_ln_kernel<false><<<lnGrid, 256>>>(
            x, y, ln1_s + (size_t)l * Hc, ln1_b + (size_t)l * Hc, x, x_h,
            cls_w, cls_b, out);
        gemm_f16_async<1><<<gFF, 256, GEMM_SMEM>>>(
            x_h, ff1w_h + (size_t)l * FFc * Hc,
            ff1_b + (size_t)l * FFc, ff_h, Mc, FFc, Hc);
        gemm_f16_async<0><<<gH, 256, GEMM_SMEM>>>(
            ff_h, ff2w_h + (size_t)l * Hc * FFc,
            ff2_b + (size_t)l * Hc, y, Mc, Hc, FFc);
        if (l == NLc - 1) {
            add_ln_kernel<true><<<lnGrid, 256>>>(
                x, y, ln2_s + (size_t)l * Hc, ln2_b + (size_t)l * Hc, x, x_h,
                cls_w, cls_b, out);
        } else {
            add_ln_kernel<false><<<lnGrid, 256>>>(
                x, y, ln2_s + (size_t)l * Hc, ln2_b + (size_t)l * Hc, x, x_h,
                cls_w, cls_b, out);
        }
    }
}